// round 6
// baseline (speedup 1.0000x reference)
#include <cuda_runtime.h>
#include <cstdint>

#define NTOK   524288     // 16*32*32*32
#define BATCH  32
#define ROWS   64         // 2 sides * 32 batch
#define NB1    8192       // buckets: float bits >> 19
#define SMARG  1024u      // sample-rank margin (true ranks: *8)
#define CAPB   16384      // per-block candidate segment
#define BUFCAP 12288      // per-block smem candidate buffer
#define SELCAP 49152      // smem-resident key cap in k_select

static __device__ __forceinline__ float clampf(float x) {
    return fminf(fmaxf(x, 1e-3f), 0.999f);
}

// ---------------- scratch ----------------
__device__ float        d_tab[2][BATCH][112];      // Ev[16] Et[32] Eh[32] Ew[32]
__device__ int          d_Kc[2];
__device__ unsigned int d_histP[ROWS][8][NB1];     // per-block hist slices (16 MB)
__device__ int          d_bHi[ROWS];
__device__ int          d_bLo[ROWS];
__device__ unsigned int d_abovePart[ROWS][4];
__device__ unsigned int d_ccPart[ROWS][4];
__device__ unsigned int d_candKey[ROWS][4 * CAPB]; // 16 MB
__device__ unsigned int d_candIdx[ROWS][4 * CAPB]; // 16 MB

// ---------------- k_init: tables + K only (tiny) ----------------
__global__ void k_init(
    const float* __restrict__ comps, const int* __restrict__ idxp,
    const float* __restrict__ ur_s, const float* __restrict__ ur_t,
    const float* __restrict__ uv_s, const float* __restrict__ ut_s,
    const float* __restrict__ uh_s, const float* __restrict__ uw_s,
    const float* __restrict__ uv_t, const float* __restrict__ ut_t,
    const float* __restrict__ uh_t, const float* __restrict__ uw_t)
{
    int id = idxp[0];
    float ia0 = 1.0f / comps[id*4+0];
    float ia1 = 1.0f / comps[id*4+1];
    float ia2 = 1.0f / comps[id*4+2];
    float ia3 = 1.0f / comps[id*4+3];
    for (int e = threadIdx.x; e < 2*BATCH*112; e += blockDim.x) {
        int side = e / (BATCH*112);
        int rem  = e % (BATCH*112);
        int b = rem / 112;
        int j = rem % 112;
        const float* uv = side ? uv_t : uv_s;
        const float* ut = side ? ut_t : ut_s;
        const float* uh = side ? uh_t : uh_s;
        const float* uw = side ? uw_t : uw_s;
        float val, ia;
        if (j < 16)      { val = uv[b*16 +  j     ]; ia = ia0; }
        else if (j < 48) { val = ut[b*32 + (j-16)]; ia = ia1; }
        else if (j < 80) { val = uh[b*32 + (j-48)]; ia = ia2; }
        else             { val = uw[b*32 + (j-80)]; ia = ia3; }
        d_tab[side][b][j] = powf(clampf(val), ia);
    }
    if (threadIdx.x == 0) d_Kc[0] = (int)(clampf(ur_s[0]) * (float)NTOK);
    if (threadIdx.x == 1) d_Kc[1] = (int)(clampf(ur_t[0]) * (float)NTOK);
}

// ---------------- k_hist: SAMPLED histogram (1/8 of tokens), private slices ----------------
__global__ void __launch_bounds__(1024) k_hist(const float* __restrict__ u0s,
                                               const float* __restrict__ u0t)
{
    __shared__ unsigned int sh[NB1];
    __shared__ float stab[112];
    int row   = blockIdx.x >> 3;
    int chunk = blockIdx.x & 7;
    int side  = row >> 5, b = row & 31;
    int t = threadIdx.x;
    for (int i = t; i < NB1; i += 1024) sh[i] = 0u;
    if (t < 112) stab[t] = d_tab[side][b][t];
    __syncthreads();

    const float4* src = (const float4*)((side ? u0t : u0s) + (size_t)b * NTOK);

    int g  = chunk * 256 + (t >> 2);     // group id in [0,2048)
    int q  = t & 3;
    int v  = g >> 7;
    int tt = (g >> 2) & 31;
    int j  = g & 3;
    int h  = (v*3 + tt*5 + j*8) & 31;
    float pre = stab[v] * stab[16+tt] * stab[48+h];
    int base4 = ((((v << 5) | tt) << 5) | h) * 8 + q * 2;
    int w = q * 8;

    float4 a = src[base4];
    float4 c = src[base4 + 1];
    float k0 = clampf(a.x) * pre * stab[80+w+0];
    float k1 = clampf(a.y) * pre * stab[80+w+1];
    float k2 = clampf(a.z) * pre * stab[80+w+2];
    float k3 = clampf(a.w) * pre * stab[80+w+3];
    float k4 = clampf(c.x) * pre * stab[80+w+4];
    float k5 = clampf(c.y) * pre * stab[80+w+5];
    float k6 = clampf(c.z) * pre * stab[80+w+6];
    float k7 = clampf(c.w) * pre * stab[80+w+7];
    atomicAdd(&sh[__float_as_uint(k0) >> 19], 1u);
    atomicAdd(&sh[__float_as_uint(k1) >> 19], 1u);
    atomicAdd(&sh[__float_as_uint(k2) >> 19], 1u);
    atomicAdd(&sh[__float_as_uint(k3) >> 19], 1u);
    atomicAdd(&sh[__float_as_uint(k4) >> 19], 1u);
    atomicAdd(&sh[__float_as_uint(k5) >> 19], 1u);
    atomicAdd(&sh[__float_as_uint(k6) >> 19], 1u);
    atomicAdd(&sh[__float_as_uint(k7) >> 19], 1u);

    __syncthreads();
    for (int i = t; i < NB1; i += 1024) d_histP[row][chunk][i] = sh[i];
}

// ---------------- k_scan: sum slices + suffix scan -> window [bLo, bHi] ----------------
__global__ void __launch_bounds__(1024) k_scan()
{
    __shared__ unsigned int wsum[32];
    __shared__ unsigned int stot;
    int row = blockIdx.x, t = threadIdx.x;

    int base_b = 8184 - 8 * t;           // 8 contiguous buckets, descending map
    unsigned int acc[8] = {0,0,0,0,0,0,0,0};
    #pragma unroll
    for (int s = 0; s < 8; s++) {
        const uint4* p = (const uint4*)&d_histP[row][s][base_b];
        uint4 a = p[0], b2 = p[1];
        acc[0] += a.x;  acc[1] += a.y;  acc[2] += a.z;  acc[3] += a.w;
        acc[4] += b2.x; acc[5] += b2.y; acc[6] += b2.z; acc[7] += b2.w;
    }
    unsigned int v[8]; unsigned int s = 0;
    #pragma unroll
    for (int i = 0; i < 8; i++) { v[i] = acc[7 - i]; s += v[i]; }  // v[i]: bucket 8191-(t*8+i)

    unsigned int x = s;
    int lane = t & 31, w = t >> 5;
    #pragma unroll
    for (int o = 1; o < 32; o <<= 1) {
        unsigned int y = __shfl_up_sync(0xffffffffu, x, o);
        if (lane >= o) x += y;
    }
    if (lane == 31) wsum[w] = x;
    __syncthreads();
    if (t < 32) {
        unsigned int y = wsum[t], z = y;
        #pragma unroll
        for (int o = 1; o < 32; o <<= 1) {
            unsigned int q = __shfl_up_sync(0xffffffffu, z, o);
            if (t >= o) z += q;
        }
        wsum[t] = z - y;                 // exclusive warp prefix
        if (t == 31) stot = z;
    }
    __syncthreads();
    unsigned int P = wsum[w] + x - s;    // samples strictly above this thread's chunk
    unsigned int K = (unsigned int)d_Kc[row >> 5];
    unsigned int sKt = K >> 3;
    unsigned int targHi = (sKt > SMARG) ? (sKt - SMARG) : 0u;
    unsigned int targLo = sKt + SMARG;
    unsigned int total = stot;
    unsigned int cum = P;
    #pragma unroll
    for (int i = 0; i < 8; i++) {
        int bb = 8191 - (t*8 + i);
        unsigned int hv = v[i];
        if (cum <= targHi && cum + hv > targHi) d_bHi[row] = bb;
        if (cum <  targLo && cum + hv >= targLo) d_bLo[row] = bb;
        cum += hv;
    }
    if (t == 0 && targLo > total) d_bLo[row] = 0;
}

// ---------------- k_mask: mask + above-count + private-segment candidate gather ----------------
extern __shared__ unsigned int mbuf[];
__global__ void __launch_bounds__(1024, 2) k_mask(const float* __restrict__ u0s,
                                                  const float* __restrict__ u0t,
                                                  float* __restrict__ out)
{
    __shared__ float stab[112];
    __shared__ unsigned int s33[33];
    __shared__ unsigned int sCnt;
    unsigned int* bKey = mbuf;
    unsigned int* bIdx = mbuf + BUFCAP;

    int row   = blockIdx.x >> 2;
    int chunk = blockIdx.x & 3;
    int side  = row >> 5, b = row & 31;
    int t = threadIdx.x;
    if (t < 112) stab[t] = d_tab[side][b][t];
    if (t == 0) sCnt = 0u;
    __syncthreads();

    unsigned int bHi = (unsigned int)d_bHi[row];
    unsigned int bLo = (unsigned int)d_bLo[row];
    unsigned long long hk = ((unsigned long long)(bHi + 1)) << 19;
    float Thif = (hk >= 0x3F800000ull) ? 1.0f : __uint_as_float((unsigned int)hk);
    float Tlof = __uint_as_float(bLo << 19);

    const float4* src = (const float4*)((side ? u0t : u0s) + (size_t)b * NTOK);
    float4* out4 = (float4*)(out + (size_t)row * NTOK);
    unsigned int* segK = &d_candKey[row][chunk * CAPB];
    unsigned int* segI = &d_candIdx[row][chunk * CAPB];
    int lane = t & 31;
    unsigned int lmask = (1u << lane) - 1u;
    unsigned int nAbove = 0;
    unsigned int gTot = 0;               // uniform across block

    // per-thread invariants: w0=(4t)&31, h=(t>>3)&31  (chunk/it strides are multiples of 2048)
    int w0 = (t << 2) & 31;
    int h  = (t >> 3) & 31;
    float hC = stab[48 + h];
    float wj0 = stab[80+w0+0] * hC;
    float wj1 = stab[80+w0+1] * hC;
    float wj2 = stab[80+w0+2] * hC;
    float wj3 = stab[80+w0+3] * hC;

    int base4 = chunk * 32768;
    for (int it = 0; it < 32; it++) {
        int idx4 = base4 + it * 1024 + t;
        float4 u = __ldcs(&src[idx4]);
        float pre = stab[idx4 >> 13] * stab[16 + ((idx4 >> 8) & 31)];
        float kf[4];
        kf[0] = clampf(u.x) * pre * wj0;
        kf[1] = clampf(u.y) * pre * wj1;
        kf[2] = clampf(u.z) * pre * wj2;
        kf[3] = clampf(u.w) * pre * wj3;
        float m[4];
        #pragma unroll
        for (int j = 0; j < 4; j++) {
            bool above = (kf[j] >= Thif);
            m[j] = above ? 1.0f : 0.0f;
            nAbove += above;
            bool cand = (!above) && (kf[j] >= Tlof);
            unsigned int mball = __ballot_sync(0xffffffffu, cand);
            if (mball) {
                int leader = __ffs(mball) - 1;
                unsigned int bp = 0;
                if (lane == leader) bp = atomicAdd(&sCnt, (unsigned int)__popc(mball));
                bp = __shfl_sync(0xffffffffu, bp, leader);
                if (cand) {
                    unsigned int pos = bp + __popc(mball & lmask);
                    if (pos < BUFCAP) {
                        bKey[pos] = __float_as_uint(kf[j]);
                        bIdx[pos] = (unsigned int)((idx4 << 2) + j);
                    }
                }
            }
        }
        out4[idx4] = make_float4(m[0], m[1], m[2], m[3]);

        __syncthreads();
        unsigned int cur = sCnt;
        if (cur >= BUFCAP - 4096u) {        // headroom for next iteration (max 4096 appends)
            for (unsigned int i = t; i < cur; i += 1024) {
                unsigned int gpos = gTot + i;
                if (gpos < CAPB) { segK[gpos] = bKey[i]; segI[gpos] = bIdx[i]; }
            }
            gTot += cur;
            __syncthreads();
            if (t == 0) sCnt = 0u;
            __syncthreads();
        }
    }
    // final flush
    {
        unsigned int cur = sCnt;
        for (unsigned int i = t; i < cur; i += 1024) {
            unsigned int gpos = gTot + i;
            if (gpos < CAPB) { segK[gpos] = bKey[i]; segI[gpos] = bIdx[i]; }
        }
        gTot += cur;
    }

    // above-count: block reduce, plain store per (row,chunk)
    unsigned int wv = __reduce_add_sync(0xffffffffu, nAbove);
    if (lane == 0) s33[t >> 5] = wv;
    __syncthreads();
    if (t < 32) {
        unsigned int z = __reduce_add_sync(0xffffffffu, s33[t]);
        if (t == 0) d_abovePart[row][chunk] = z;
    }
    if (t == 1) d_ccPart[row][chunk] = (gTot < CAPB) ? gTot : CAPB;
}

// ---------------- block reduce helper (fallback path only) ----------------
static __device__ __forceinline__ unsigned int blk_reduce_1024(unsigned int v, unsigned int* s33)
{
    unsigned int wv = __reduce_add_sync(0xffffffffu, v);
    int lane = threadIdx.x & 31, w = threadIdx.x >> 5;
    __syncthreads();
    if (lane == 0) s33[w] = wv;
    __syncthreads();
    if (threadIdx.x < 32) {
        unsigned int x = s33[threadIdx.x];
        x = __reduce_add_sync(0xffffffffu, x);
        if (threadIdx.x == 0) s33[32] = x;
    }
    __syncthreads();
    return s33[32];
}

// ---------------- k_select: radix-descent exact threshold + tie-break (4 segments) ----------------
extern __shared__ unsigned int selk[];
__global__ void __launch_bounds__(1024) k_select(float* __restrict__ out)
{
    __shared__ unsigned int hcnt[1024];
    __shared__ unsigned int wsum[32];
    __shared__ unsigned int sSel, sRnew;
    __shared__ unsigned int eqIdx[2048];
    __shared__ unsigned int eqCnt;
    __shared__ unsigned int sIstar;
    __shared__ unsigned int s33[33];

    int row = blockIdx.x, t = threadIdx.x;
    unsigned int cnt[4], off[4];
    unsigned int c = 0, above = 0;
    #pragma unroll
    for (int s = 0; s < 4; s++) {
        unsigned int cs = d_ccPart[row][s];
        cnt[s] = (cs < CAPB) ? cs : CAPB;
        off[s] = c;
        c += cnt[s];
        above += d_abovePart[row][s];
    }
    unsigned int K = (unsigned int)d_Kc[row >> 5];
    int R = (int)K - (int)above;
    const unsigned int* gk = d_candKey[row];
    const unsigned int* gi = d_candIdx[row];
    float* orow = out + (size_t)row * NTOK;
    if (R <= 0) return;
    if ((unsigned int)R >= c) {
        #pragma unroll
        for (int s = 0; s < 4; s++)
            for (unsigned int i = t; i < cnt[s]; i += 1024)
                orow[gi[s*CAPB + i]] = 1.0f;
        return;
    }

    bool insm = (c <= SELCAP);
    if (insm) {
        #pragma unroll
        for (int s = 0; s < 4; s++)
            for (unsigned int i = t; i < cnt[s]; i += 1024)
                selk[off[s] + i] = gk[s*CAPB + i];
        __syncthreads();
    }

    unsigned int bLo = (unsigned int)d_bLo[row], bHi = (unsigned int)d_bHi[row];
    unsigned int base = bLo << 19;
    unsigned long long Wd = ((unsigned long long)(bHi + 1u - bLo)) << 19;
    int sb = (Wd <= 1ull) ? 0 : (64 - __clzll(Wd - 1ull));
    if (sb > 32) sb = 32;
    unsigned int Rcur = (unsigned int)R;

    while (sb > 0) {
        int bits = sb >= 10 ? 10 : sb;
        int shift = sb - bits;
        hcnt[t] = 0u;
        __syncthreads();
        unsigned int spanm = (sb >= 32) ? 0xFFFFFFFFu : ((1u << sb) - 1u);
        if (insm) {
            for (unsigned int i = t; i < c; i += 1024) {
                unsigned int k = selk[i];
                unsigned int d = k - base;
                if (k >= base && d <= spanm) atomicAdd(&hcnt[d >> shift], 1u);
            }
        } else {
            #pragma unroll
            for (int s = 0; s < 4; s++)
                for (unsigned int i = t; i < cnt[s]; i += 1024) {
                    unsigned int k = gk[s*CAPB + i];
                    unsigned int d = k - base;
                    if (k >= base && d <= spanm) atomicAdd(&hcnt[d >> shift], 1u);
                }
        }
        __syncthreads();
        unsigned int x = hcnt[1023 - t];
        unsigned int cb = x;
        int lane = t & 31, w = t >> 5;
        #pragma unroll
        for (int o = 1; o < 32; o <<= 1) {
            unsigned int y = __shfl_up_sync(0xffffffffu, x, o);
            if (lane >= o) x += y;
        }
        if (lane == 31) wsum[w] = x;
        __syncthreads();
        if (t < 32) {
            unsigned int y = wsum[t], z = y;
            #pragma unroll
            for (int o = 1; o < 32; o <<= 1) {
                unsigned int q = __shfl_up_sync(0xffffffffu, z, o);
                if (t >= o) z += q;
            }
            wsum[t] = z - y;
        }
        __syncthreads();
        unsigned int incl = wsum[w] + x;
        unsigned int A = incl - cb;
        if (A < Rcur && Rcur <= incl) { sSel = (unsigned int)(1023 - t); sRnew = Rcur - A; }
        __syncthreads();
        base += sSel << shift;
        Rcur = sRnew;
        sb = shift;
        __syncthreads();
    }
    unsigned int Tkey = base;
    unsigned int R3 = Rcur;   // rank among equal keys (stable by index), >= 1

    if (t == 0) eqCnt = 0u;
    __syncthreads();
    #pragma unroll
    for (int s = 0; s < 4; s++)
        for (unsigned int i = t; i < cnt[s]; i += 1024) {
            unsigned int k = insm ? selk[off[s] + i] : gk[s*CAPB + i];
            if (k == Tkey) {
                unsigned int p = atomicAdd(&eqCnt, 1u);
                if (p < 2048) eqIdx[p] = gi[s*CAPB + i];
            }
        }
    __syncthreads();
    unsigned int e = eqCnt;
    unsigned int Istar;
    if (e <= 2048) {
        for (unsigned int j = t; j < e; j += 1024) {
            unsigned int my = eqIdx[j], r = 0;
            for (unsigned int m = 0; m < e; m++) r += (eqIdx[m] < my);
            if (r == R3 - 1u) sIstar = my;
        }
        __syncthreads();
        Istar = sIstar;
    } else {
        unsigned int ilo = 0, ihi = NTOK - 1;
        while (ilo < ihi) {
            unsigned int mid = (ilo + ihi) >> 1;
            unsigned int l2 = 0;
            #pragma unroll
            for (int s = 0; s < 4; s++)
                for (unsigned int i = t; i < cnt[s]; i += 1024) {
                    unsigned int k = insm ? selk[off[s] + i] : gk[s*CAPB + i];
                    if (k == Tkey) l2 += (gi[s*CAPB + i] <= mid);
                }
            unsigned int cc2 = blk_reduce_1024(l2, s33);
            if (cc2 >= R3) ihi = mid; else ilo = mid + 1u;
        }
        Istar = ilo;
    }

    #pragma unroll
    for (int s = 0; s < 4; s++)
        for (unsigned int i = t; i < cnt[s]; i += 1024) {
            unsigned int k = insm ? selk[off[s] + i] : gk[s*CAPB + i];
            if (k > Tkey || (k == Tkey && gi[s*CAPB + i] <= Istar))
                orow[gi[s*CAPB + i]] = 1.0f;
        }
}

// ---------------- launch ----------------
extern "C" void kernel_launch(void* const* d_in, const int* in_sizes, int n_in,
                              void* d_out, int out_size)
{
    const float* comps = (const float*)d_in[0];
    const float* ur_s  = (const float*)d_in[1];
    const float* ur_t  = (const float*)d_in[2];
    const float* u0s   = (const float*)d_in[3];
    const float* u0t   = (const float*)d_in[4];
    const float* uv_s  = (const float*)d_in[5];
    const float* ut_s  = (const float*)d_in[6];
    const float* uh_s  = (const float*)d_in[7];
    const float* uw_s  = (const float*)d_in[8];
    const float* uv_t  = (const float*)d_in[9];
    const float* ut_t  = (const float*)d_in[10];
    const float* uh_t  = (const float*)d_in[11];
    const float* uw_t  = (const float*)d_in[12];
    const int*   idx   = (const int*)d_in[13];
    float* out = (float*)d_out;

    static int attr_done = 0;
    if (!attr_done) {
        cudaFuncSetAttribute(k_mask, cudaFuncAttributeMaxDynamicSharedMemorySize,
                             BUFCAP * 2 * sizeof(unsigned int));
        cudaFuncSetAttribute(k_select, cudaFuncAttributeMaxDynamicSharedMemorySize,
                             SELCAP * sizeof(unsigned int));
        attr_done = 1;
    }

    k_init<<<1, 256>>>(comps, idx, ur_s, ur_t,
                       uv_s, ut_s, uh_s, uw_s,
                       uv_t, ut_t, uh_t, uw_t);
    k_hist<<<512, 1024>>>(u0s, u0t);
    k_scan<<<64, 1024>>>();
    k_mask<<<256, 1024, BUFCAP * 2 * sizeof(unsigned int)>>>(u0s, u0t, out);
    k_select<<<64, 1024, SELCAP * sizeof(unsigned int)>>>(out);
}

// round 7
// speedup vs baseline: 1.0661x; 1.0661x over previous
#include <cuda_runtime.h>
#include <cstdint>

#define NTOK   524288     // 16*32*32*32
#define BATCH  32
#define ROWS   64         // 2 sides * 32 batch
#define NB1    8192       // buckets: float bits >> 19
#define SMARG  1024u      // sample-rank margin (true ranks: *8)
#define NSEG   8          // candidate segments per row (= k_mask chunks)
#define CAPB   8192       // per-segment candidate capacity
#define BUFCAP 6144       // per-block smem candidate buffer
#define SELCAP 49152      // smem-resident key cap in k_select

static __device__ __forceinline__ float clampf(float x) {
    return fminf(fmaxf(x, 1e-3f), 0.999f);
}

// ---------------- scratch ----------------
__device__ float        d_tab[2][BATCH][112];         // Ev[16] Et[32] Eh[32] Ew[32]
__device__ int          d_Kc[2];
__device__ unsigned int d_hist[ROWS][NB1];            // 2 MB, zeroed by k_init
__device__ int          d_bHi[ROWS];
__device__ int          d_bLo[ROWS];
__device__ unsigned int d_abovePart[ROWS][NSEG];
__device__ unsigned int d_ccPart[ROWS][NSEG];
__device__ unsigned int d_candKey[ROWS][NSEG * CAPB]; // 16 MB
__device__ unsigned int d_candIdx[ROWS][NSEG * CAPB]; // 16 MB

// ---------------- k_init: zero hist + (block 0) tables & K ----------------
__global__ void __launch_bounds__(1024) k_init(
    const float* __restrict__ comps, const int* __restrict__ idxp,
    const float* __restrict__ ur_s, const float* __restrict__ ur_t,
    const float* __restrict__ uv_s, const float* __restrict__ ut_s,
    const float* __restrict__ uh_s, const float* __restrict__ uw_s,
    const float* __restrict__ uv_t, const float* __restrict__ ut_t,
    const float* __restrict__ uh_t, const float* __restrict__ uw_t)
{
    unsigned int* hp = (unsigned int*)d_hist;
    for (int i = blockIdx.x * 1024 + threadIdx.x; i < ROWS * NB1; i += 64 * 1024)
        hp[i] = 0u;

    if (blockIdx.x == 0) {
        int id = idxp[0];
        float ia0 = 1.0f / comps[id*4+0];
        float ia1 = 1.0f / comps[id*4+1];
        float ia2 = 1.0f / comps[id*4+2];
        float ia3 = 1.0f / comps[id*4+3];
        for (int e = threadIdx.x; e < 2*BATCH*112; e += 1024) {
            int side = e / (BATCH*112);
            int rem  = e % (BATCH*112);
            int b = rem / 112;
            int j = rem % 112;
            const float* uv = side ? uv_t : uv_s;
            const float* ut = side ? ut_t : ut_s;
            const float* uh = side ? uh_t : uh_s;
            const float* uw = side ? uw_t : uw_s;
            float val, ia;
            if (j < 16)      { val = uv[b*16 +  j     ]; ia = ia0; }
            else if (j < 48) { val = ut[b*32 + (j-16)]; ia = ia1; }
            else if (j < 80) { val = uh[b*32 + (j-48)]; ia = ia2; }
            else             { val = uw[b*32 + (j-80)]; ia = ia3; }
            d_tab[side][b][j] = powf(clampf(val), ia);
        }
        if (threadIdx.x == 0) d_Kc[0] = (int)(clampf(ur_s[0]) * (float)NTOK);
        if (threadIdx.x == 1) d_Kc[1] = (int)(clampf(ur_t[0]) * (float)NTOK);
    }
}

// ---------------- k_hist: SAMPLED histogram (1/8 of tokens), sparse merge ----------------
__global__ void __launch_bounds__(1024) k_hist(const float* __restrict__ u0s,
                                               const float* __restrict__ u0t)
{
    __shared__ unsigned int sh[NB1];
    __shared__ float stab[112];
    int row   = blockIdx.x >> 3;
    int chunk = blockIdx.x & 7;
    int side  = row >> 5, b = row & 31;
    int t = threadIdx.x;
    for (int i = t; i < NB1; i += 1024) sh[i] = 0u;
    if (t < 112) stab[t] = d_tab[side][b][t];
    __syncthreads();

    const float4* src = (const float4*)((side ? u0t : u0s) + (size_t)b * NTOK);

    int g  = chunk * 256 + (t >> 2);     // group id in [0,2048)
    int q  = t & 3;
    int v  = g >> 7;
    int tt = (g >> 2) & 31;
    int j  = g & 3;
    int h  = (v*3 + tt*5 + j*8) & 31;
    float pre = stab[v] * stab[16+tt] * stab[48+h];
    int base4 = ((((v << 5) | tt) << 5) | h) * 8 + q * 2;
    int w = q * 8;

    float4 a = src[base4];
    float4 c = src[base4 + 1];
    float k0 = clampf(a.x) * pre * stab[80+w+0];
    float k1 = clampf(a.y) * pre * stab[80+w+1];
    float k2 = clampf(a.z) * pre * stab[80+w+2];
    float k3 = clampf(a.w) * pre * stab[80+w+3];
    float k4 = clampf(c.x) * pre * stab[80+w+4];
    float k5 = clampf(c.y) * pre * stab[80+w+5];
    float k6 = clampf(c.z) * pre * stab[80+w+6];
    float k7 = clampf(c.w) * pre * stab[80+w+7];
    atomicAdd(&sh[__float_as_uint(k0) >> 19], 1u);
    atomicAdd(&sh[__float_as_uint(k1) >> 19], 1u);
    atomicAdd(&sh[__float_as_uint(k2) >> 19], 1u);
    atomicAdd(&sh[__float_as_uint(k3) >> 19], 1u);
    atomicAdd(&sh[__float_as_uint(k4) >> 19], 1u);
    atomicAdd(&sh[__float_as_uint(k5) >> 19], 1u);
    atomicAdd(&sh[__float_as_uint(k6) >> 19], 1u);
    atomicAdd(&sh[__float_as_uint(k7) >> 19], 1u);

    __syncthreads();
    for (int i = t; i < NB1; i += 1024)
        if (sh[i]) atomicAdd(&d_hist[row][i], sh[i]);
}

// ---------------- k_scan: suffix scan -> window [bLo, bHi] ----------------
__global__ void __launch_bounds__(1024) k_scan()
{
    __shared__ unsigned int wsum[32];
    __shared__ unsigned int stot;
    int row = blockIdx.x, t = threadIdx.x;
    const unsigned int* hist = d_hist[row];
    unsigned int v[8]; unsigned int s = 0;
    #pragma unroll
    for (int i = 0; i < 8; i++) { v[i] = hist[8191 - (t*8 + i)]; s += v[i]; }
    unsigned int x = s;
    int lane = t & 31, w = t >> 5;
    #pragma unroll
    for (int o = 1; o < 32; o <<= 1) {
        unsigned int y = __shfl_up_sync(0xffffffffu, x, o);
        if (lane >= o) x += y;
    }
    if (lane == 31) wsum[w] = x;
    __syncthreads();
    if (t < 32) {
        unsigned int y = wsum[t], z = y;
        #pragma unroll
        for (int o = 1; o < 32; o <<= 1) {
            unsigned int q = __shfl_up_sync(0xffffffffu, z, o);
            if (t >= o) z += q;
        }
        wsum[t] = z - y;                 // exclusive warp prefix
        if (t == 31) stot = z;
    }
    __syncthreads();
    unsigned int P = wsum[w] + x - s;    // samples strictly above this thread's chunk
    unsigned int K = (unsigned int)d_Kc[row >> 5];
    unsigned int sKt = K >> 3;
    unsigned int targHi = (sKt > SMARG) ? (sKt - SMARG) : 0u;
    unsigned int targLo = sKt + SMARG;
    unsigned int total = stot;
    unsigned int cum = P;
    #pragma unroll
    for (int i = 0; i < 8; i++) {
        int bb = 8191 - (t*8 + i);
        unsigned int hv = v[i];
        if (cum <= targHi && cum + hv > targHi) d_bHi[row] = bb;
        if (cum <  targLo && cum + hv >= targLo) d_bLo[row] = bb;
        cum += hv;
    }
    if (t == 0 && targLo > total) d_bLo[row] = 0;
}

// ---------------- k_mask: 512-thread blocks, aggregated append, private segments ----------------
extern __shared__ unsigned int mbuf[];
__global__ void __launch_bounds__(512, 3) k_mask(const float* __restrict__ u0s,
                                                 const float* __restrict__ u0t,
                                                 float* __restrict__ out)
{
    __shared__ float stab[112];
    __shared__ unsigned int s17[17];
    __shared__ unsigned int sCnt;
    unsigned int* bKey = mbuf;
    unsigned int* bIdx = mbuf + BUFCAP;

    int row   = blockIdx.x >> 3;
    int chunk = blockIdx.x & 7;
    int side  = row >> 5, b = row & 31;
    int t = threadIdx.x;
    if (t < 112) stab[t] = d_tab[side][b][t];
    if (t == 0) sCnt = 0u;
    __syncthreads();

    unsigned int bHi = (unsigned int)d_bHi[row];
    unsigned int bLo = (unsigned int)d_bLo[row];
    unsigned long long hk = ((unsigned long long)(bHi + 1)) << 19;
    float Thif = (hk >= 0x3F800000ull) ? 1.0f : __uint_as_float((unsigned int)hk);
    float Tlof = __uint_as_float(bLo << 19);

    const float4* src = (const float4*)((side ? u0t : u0s) + (size_t)b * NTOK);
    float4* out4 = (float4*)(out + (size_t)row * NTOK);
    unsigned int* segK = &d_candKey[row][chunk * CAPB];
    unsigned int* segI = &d_candIdx[row][chunk * CAPB];
    int lane = t & 31;
    unsigned int lmask = (1u << lane) - 1u;
    unsigned int nAbove = 0;
    unsigned int gTot = 0;               // uniform across block

    // per-thread invariants: strides (512, 16384) are multiples of 8 in float4 units
    int w0 = (t << 2) & 31;
    int h  = (t >> 3) & 31;
    float hC = stab[48 + h];
    float wj0 = stab[80+w0+0] * hC;
    float wj1 = stab[80+w0+1] * hC;
    float wj2 = stab[80+w0+2] * hC;
    float wj3 = stab[80+w0+3] * hC;

    int base4 = chunk * 16384;
    for (int it = 0; it < 32; it++) {
        int idx4 = base4 + it * 512 + t;
        float4 u = __ldcs(&src[idx4]);
        float pre = stab[idx4 >> 13] * stab[16 + ((idx4 >> 8) & 31)];
        float k0 = clampf(u.x) * pre * wj0;
        float k1 = clampf(u.y) * pre * wj1;
        float k2 = clampf(u.z) * pre * wj2;
        float k3 = clampf(u.w) * pre * wj3;

        bool a0 = (k0 >= Thif), a1 = (k1 >= Thif), a2 = (k2 >= Thif), a3 = (k3 >= Thif);
        nAbove += (unsigned int)a0 + a1 + a2 + a3;
        unsigned int cm = (unsigned int)(!a0 && k0 >= Tlof)
                        | ((unsigned int)(!a1 && k1 >= Tlof) << 1)
                        | ((unsigned int)(!a2 && k2 >= Tlof) << 2)
                        | ((unsigned int)(!a3 && k3 >= Tlof) << 3);

        // single aggregated append per warp
        unsigned int b0 = __ballot_sync(0xffffffffu, cm & 1u);
        unsigned int b1 = __ballot_sync(0xffffffffu, cm & 2u);
        unsigned int b2 = __ballot_sync(0xffffffffu, cm & 4u);
        unsigned int b3 = __ballot_sync(0xffffffffu, cm & 8u);
        unsigned int c0 = __popc(b0), c1 = __popc(b1), c2 = __popc(b2), c3 = __popc(b3);
        unsigned int tot = c0 + c1 + c2 + c3;
        if (tot) {
            unsigned int bp = 0;
            if (lane == 0) bp = atomicAdd(&sCnt, tot);
            bp = __shfl_sync(0xffffffffu, bp, 0);
            int n = idx4 << 2;
            if (cm & 1u) { unsigned int p = bp + __popc(b0 & lmask);
                if (p < BUFCAP) { bKey[p] = __float_as_uint(k0); bIdx[p] = (unsigned int)n; } }
            if (cm & 2u) { unsigned int p = bp + c0 + __popc(b1 & lmask);
                if (p < BUFCAP) { bKey[p] = __float_as_uint(k1); bIdx[p] = (unsigned int)(n + 1); } }
            if (cm & 4u) { unsigned int p = bp + c0 + c1 + __popc(b2 & lmask);
                if (p < BUFCAP) { bKey[p] = __float_as_uint(k2); bIdx[p] = (unsigned int)(n + 2); } }
            if (cm & 8u) { unsigned int p = bp + c0 + c1 + c2 + __popc(b3 & lmask);
                if (p < BUFCAP) { bKey[p] = __float_as_uint(k3); bIdx[p] = (unsigned int)(n + 3); } }
        }

        __stcs(&out4[idx4], make_float4(a0 ? 1.0f : 0.0f, a1 ? 1.0f : 0.0f,
                                        a2 ? 1.0f : 0.0f, a3 ? 1.0f : 0.0f));

        // flush check every 2 iterations (max growth 2*512*4 = 4096; keep <= BUFCAP-4096)
        if (it & 1) {
            __syncthreads();
            unsigned int cur = sCnt;
            if (cur > BUFCAP - 4096u) {
                for (unsigned int i = t; i < cur; i += 512) {
                    unsigned int gpos = gTot + i;
                    if (gpos < CAPB) { segK[gpos] = bKey[i]; segI[gpos] = bIdx[i]; }
                }
                gTot += cur;
                __syncthreads();
                if (t == 0) sCnt = 0u;
                __syncthreads();
            }
        }
    }
    // final flush
    __syncthreads();
    {
        unsigned int cur = sCnt;
        for (unsigned int i = t; i < cur; i += 512) {
            unsigned int gpos = gTot + i;
            if (gpos < CAPB) { segK[gpos] = bKey[i]; segI[gpos] = bIdx[i]; }
        }
        gTot += cur;
    }

    // above-count: block reduce, plain store per (row,chunk)
    unsigned int wv = __reduce_add_sync(0xffffffffu, nAbove);
    if (lane == 0) s17[t >> 5] = wv;
    __syncthreads();
    if (t < 16) {
        unsigned int z = s17[t];
        #pragma unroll
        for (int o = 8; o > 0; o >>= 1) z += __shfl_down_sync(0xffffu, z, o);
        if (t == 0) d_abovePart[row][chunk] = z;
    }
    if (t == 16) d_ccPart[row][chunk] = (gTot < CAPB) ? gTot : CAPB;
}

// ---------------- block reduce helper (fallback path only) ----------------
static __device__ __forceinline__ unsigned int blk_reduce_1024(unsigned int v, unsigned int* s33)
{
    unsigned int wv = __reduce_add_sync(0xffffffffu, v);
    int lane = threadIdx.x & 31, w = threadIdx.x >> 5;
    __syncthreads();
    if (lane == 0) s33[w] = wv;
    __syncthreads();
    if (threadIdx.x < 32) {
        unsigned int x = s33[threadIdx.x];
        x = __reduce_add_sync(0xffffffffu, x);
        if (threadIdx.x == 0) s33[32] = x;
    }
    __syncthreads();
    return s33[32];
}

// ---------------- k_select: radix-descent exact threshold + tie-break (8 segments) ----------------
extern __shared__ unsigned int selk[];
__global__ void __launch_bounds__(1024) k_select(float* __restrict__ out)
{
    __shared__ unsigned int hcnt[1024];
    __shared__ unsigned int wsum[32];
    __shared__ unsigned int sSel, sRnew;
    __shared__ unsigned int eqIdx[2048];
    __shared__ unsigned int eqCnt;
    __shared__ unsigned int sIstar;
    __shared__ unsigned int s33[33];

    int row = blockIdx.x, t = threadIdx.x;
    unsigned int cnt[NSEG], off[NSEG];
    unsigned int c = 0, above = 0;
    #pragma unroll
    for (int s = 0; s < NSEG; s++) {
        unsigned int cs = d_ccPart[row][s];
        cnt[s] = (cs < CAPB) ? cs : CAPB;
        off[s] = c;
        c += cnt[s];
        above += d_abovePart[row][s];
    }
    unsigned int K = (unsigned int)d_Kc[row >> 5];
    int R = (int)K - (int)above;
    const unsigned int* gk = d_candKey[row];
    const unsigned int* gi = d_candIdx[row];
    float* orow = out + (size_t)row * NTOK;
    if (R <= 0) return;
    if ((unsigned int)R >= c) {
        #pragma unroll
        for (int s = 0; s < NSEG; s++)
            for (unsigned int i = t; i < cnt[s]; i += 1024)
                orow[gi[s*CAPB + i]] = 1.0f;
        return;
    }

    bool insm = (c <= SELCAP);
    if (insm) {
        #pragma unroll
        for (int s = 0; s < NSEG; s++)
            for (unsigned int i = t; i < cnt[s]; i += 1024)
                selk[off[s] + i] = gk[s*CAPB + i];
        __syncthreads();
    }

    unsigned int bLo = (unsigned int)d_bLo[row], bHi = (unsigned int)d_bHi[row];
    unsigned int base = bLo << 19;
    unsigned long long Wd = ((unsigned long long)(bHi + 1u - bLo)) << 19;
    int sb = (Wd <= 1ull) ? 0 : (64 - __clzll(Wd - 1ull));
    if (sb > 32) sb = 32;
    unsigned int Rcur = (unsigned int)R;

    while (sb > 0) {
        int bits = sb >= 10 ? 10 : sb;
        int shift = sb - bits;
        hcnt[t] = 0u;
        __syncthreads();
        unsigned int spanm = (sb >= 32) ? 0xFFFFFFFFu : ((1u << sb) - 1u);
        if (insm) {
            for (unsigned int i = t; i < c; i += 1024) {
                unsigned int k = selk[i];
                unsigned int d = k - base;
                if (k >= base && d <= spanm) atomicAdd(&hcnt[d >> shift], 1u);
            }
        } else {
            #pragma unroll
            for (int s = 0; s < NSEG; s++)
                for (unsigned int i = t; i < cnt[s]; i += 1024) {
                    unsigned int k = gk[s*CAPB + i];
                    unsigned int d = k - base;
                    if (k >= base && d <= spanm) atomicAdd(&hcnt[d >> shift], 1u);
                }
        }
        __syncthreads();
        unsigned int x = hcnt[1023 - t];
        unsigned int cb = x;
        int lane = t & 31, w = t >> 5;
        #pragma unroll
        for (int o = 1; o < 32; o <<= 1) {
            unsigned int y = __shfl_up_sync(0xffffffffu, x, o);
            if (lane >= o) x += y;
        }
        if (lane == 31) wsum[w] = x;
        __syncthreads();
        if (t < 32) {
            unsigned int y = wsum[t], z = y;
            #pragma unroll
            for (int o = 1; o < 32; o <<= 1) {
                unsigned int q = __shfl_up_sync(0xffffffffu, z, o);
                if (t >= o) z += q;
            }
            wsum[t] = z - y;
        }
        __syncthreads();
        unsigned int incl = wsum[w] + x;
        unsigned int A = incl - cb;
        if (A < Rcur && Rcur <= incl) { sSel = (unsigned int)(1023 - t); sRnew = Rcur - A; }
        __syncthreads();
        base += sSel << shift;
        Rcur = sRnew;
        sb = shift;
        __syncthreads();
    }
    unsigned int Tkey = base;
    unsigned int R3 = Rcur;   // rank among equal keys (stable by index), >= 1

    if (t == 0) eqCnt = 0u;
    __syncthreads();
    #pragma unroll
    for (int s = 0; s < NSEG; s++)
        for (unsigned int i = t; i < cnt[s]; i += 1024) {
            unsigned int k = insm ? selk[off[s] + i] : gk[s*CAPB + i];
            if (k == Tkey) {
                unsigned int p = atomicAdd(&eqCnt, 1u);
                if (p < 2048) eqIdx[p] = gi[s*CAPB + i];
            }
        }
    __syncthreads();
    unsigned int e = eqCnt;
    unsigned int Istar;
    if (e <= 2048) {
        for (unsigned int j = t; j < e; j += 1024) {
            unsigned int my = eqIdx[j], r = 0;
            for (unsigned int m = 0; m < e; m++) r += (eqIdx[m] < my);
            if (r == R3 - 1u) sIstar = my;
        }
        __syncthreads();
        Istar = sIstar;
    } else {
        unsigned int ilo = 0, ihi = NTOK - 1;
        while (ilo < ihi) {
            unsigned int mid = (ilo + ihi) >> 1;
            unsigned int l2 = 0;
            #pragma unroll
            for (int s = 0; s < NSEG; s++)
                for (unsigned int i = t; i < cnt[s]; i += 1024) {
                    unsigned int k = insm ? selk[off[s] + i] : gk[s*CAPB + i];
                    if (k == Tkey) l2 += (gi[s*CAPB + i] <= mid);
                }
            unsigned int cc2 = blk_reduce_1024(l2, s33);
            if (cc2 >= R3) ihi = mid; else ilo = mid + 1u;
        }
        Istar = ilo;
    }

    #pragma unroll
    for (int s = 0; s < NSEG; s++)
        for (unsigned int i = t; i < cnt[s]; i += 1024) {
            unsigned int k = insm ? selk[off[s] + i] : gk[s*CAPB + i];
            if (k > Tkey || (k == Tkey && gi[s*CAPB + i] <= Istar))
                orow[gi[s*CAPB + i]] = 1.0f;
        }
}

// ---------------- launch ----------------
extern "C" void kernel_launch(void* const* d_in, const int* in_sizes, int n_in,
                              void* d_out, int out_size)
{
    const float* comps = (const float*)d_in[0];
    const float* ur_s  = (const float*)d_in[1];
    const float* ur_t  = (const float*)d_in[2];
    const float* u0s   = (const float*)d_in[3];
    const float* u0t   = (const float*)d_in[4];
    const float* uv_s  = (const float*)d_in[5];
    const float* ut_s  = (const float*)d_in[6];
    const float* uh_s  = (const float*)d_in[7];
    const float* uw_s  = (const float*)d_in[8];
    const float* uv_t  = (const float*)d_in[9];
    const float* ut_t  = (const float*)d_in[10];
    const float* uh_t  = (const float*)d_in[11];
    const float* uw_t  = (const float*)d_in[12];
    const int*   idx   = (const int*)d_in[13];
    float* out = (float*)d_out;

    static int attr_done = 0;
    if (!attr_done) {
        cudaFuncSetAttribute(k_mask, cudaFuncAttributeMaxDynamicSharedMemorySize,
                             BUFCAP * 2 * sizeof(unsigned int));
        cudaFuncSetAttribute(k_select, cudaFuncAttributeMaxDynamicSharedMemorySize,
                             SELCAP * sizeof(unsigned int));
        attr_done = 1;
    }

    k_init<<<64, 1024>>>(comps, idx, ur_s, ur_t,
                         uv_s, ut_s, uh_s, uw_s,
                         uv_t, ut_t, uh_t, uw_t);
    k_hist<<<512, 1024>>>(u0s, u0t);
    k_scan<<<64, 1024>>>();
    k_mask<<<512, 512, BUFCAP * 2 * sizeof(unsigned int)>>>(u0s, u0t, out);
    k_select<<<64, 1024, SELCAP * sizeof(unsigned int)>>>(out);
}

// round 8
// speedup vs baseline: 1.2263x; 1.1503x over previous
#include <cuda_runtime.h>
#include <cstdint>

#define NTOK   524288     // 16*32*32*32
#define BATCH  32
#define ROWS   64         // 2 sides * 32 batch
#define NB1    8192       // buckets: float bits >> 19
#define SMARG  1024u      // sample-rank margin (true ranks: *8)
#define NSEG   8          // candidate segments per row (= k_mask chunks)
#define CAPB   8192       // per-segment candidate capacity
#define BUFCAP 12288      // per-block smem candidate buffer
#define SELCAP 49152      // smem-resident key cap in k_select

static __device__ __forceinline__ float clampf(float x) {
    return fminf(fmaxf(x, 1e-3f), 0.999f);
}

// ---------------- scratch ----------------
__device__ float        d_tab[2][BATCH][112];         // Ev[16] Et[32] Eh[32] Ew[32]
__device__ int          d_Kc[2];
__device__ int          d_bHi[ROWS];
__device__ int          d_bLo[ROWS];
__device__ unsigned int d_abovePart[ROWS][NSEG];
__device__ unsigned int d_ccPart[ROWS][NSEG];
__device__ unsigned int d_candKey[ROWS][NSEG * CAPB]; // 16 MB
__device__ unsigned int d_candIdx[ROWS][NSEG * CAPB]; // 16 MB

// ---------------- k_init: tables + K (tiny) ----------------
__global__ void k_init(
    const float* __restrict__ comps, const int* __restrict__ idxp,
    const float* __restrict__ ur_s, const float* __restrict__ ur_t,
    const float* __restrict__ uv_s, const float* __restrict__ ut_s,
    const float* __restrict__ uh_s, const float* __restrict__ uw_s,
    const float* __restrict__ uv_t, const float* __restrict__ ut_t,
    const float* __restrict__ uh_t, const float* __restrict__ uw_t)
{
    int id = idxp[0];
    float ia0 = 1.0f / comps[id*4+0];
    float ia1 = 1.0f / comps[id*4+1];
    float ia2 = 1.0f / comps[id*4+2];
    float ia3 = 1.0f / comps[id*4+3];
    for (int e = threadIdx.x; e < 2*BATCH*112; e += blockDim.x) {
        int side = e / (BATCH*112);
        int rem  = e % (BATCH*112);
        int b = rem / 112;
        int j = rem % 112;
        const float* uv = side ? uv_t : uv_s;
        const float* ut = side ? ut_t : ut_s;
        const float* uh = side ? uh_t : uh_s;
        const float* uw = side ? uw_t : uw_s;
        float val, ia;
        if (j < 16)      { val = uv[b*16 +  j     ]; ia = ia0; }
        else if (j < 48) { val = ut[b*32 + (j-16)]; ia = ia1; }
        else if (j < 80) { val = uh[b*32 + (j-48)]; ia = ia2; }
        else             { val = uw[b*32 + (j-80)]; ia = ia3; }
        d_tab[side][b][j] = powf(clampf(val), ia);
    }
    if (threadIdx.x == 0) d_Kc[0] = (int)(clampf(ur_s[0]) * (float)NTOK);
    if (threadIdx.x == 1) d_Kc[1] = (int)(clampf(ur_t[0]) * (float)NTOK);
}

// ---------------- k_histscan: sampled hist (1/8) + suffix scan, fused, 1 block/row ----------------
__global__ void __launch_bounds__(1024) k_histscan(const float* __restrict__ u0s,
                                                   const float* __restrict__ u0t)
{
    __shared__ unsigned int sh[NB1];
    __shared__ float stab[112];
    __shared__ unsigned int wsum[32];
    __shared__ unsigned int stot;
    int row  = blockIdx.x;
    int side = row >> 5, b = row & 31;
    int t = threadIdx.x;
    for (int i = t; i < NB1; i += 1024) sh[i] = 0u;
    if (t < 112) stab[t] = d_tab[side][b][t];
    __syncthreads();

    const float4* src = (const float4*)((side ? u0t : u0s) + (size_t)b * NTOK);

    // 2048 groups of 32 consecutive tokens; 8 passes of 256 groups
    for (int ch = 0; ch < 8; ch++) {
        int g  = ch * 256 + (t >> 2);
        int q  = t & 3;
        int v  = g >> 7;
        int tt = (g >> 2) & 31;
        int j  = g & 3;
        int h  = (v*3 + tt*5 + j*8) & 31;
        float pre = stab[v] * stab[16+tt] * stab[48+h];
        int base4 = ((((v << 5) | tt) << 5) | h) * 8 + q * 2;
        int w = q * 8;

        float4 a = src[base4];
        float4 c = src[base4 + 1];
        float k0 = clampf(a.x) * pre * stab[80+w+0];
        float k1 = clampf(a.y) * pre * stab[80+w+1];
        float k2 = clampf(a.z) * pre * stab[80+w+2];
        float k3 = clampf(a.w) * pre * stab[80+w+3];
        float k4 = clampf(c.x) * pre * stab[80+w+4];
        float k5 = clampf(c.y) * pre * stab[80+w+5];
        float k6 = clampf(c.z) * pre * stab[80+w+6];
        float k7 = clampf(c.w) * pre * stab[80+w+7];
        atomicAdd(&sh[__float_as_uint(k0) >> 19], 1u);
        atomicAdd(&sh[__float_as_uint(k1) >> 19], 1u);
        atomicAdd(&sh[__float_as_uint(k2) >> 19], 1u);
        atomicAdd(&sh[__float_as_uint(k3) >> 19], 1u);
        atomicAdd(&sh[__float_as_uint(k4) >> 19], 1u);
        atomicAdd(&sh[__float_as_uint(k5) >> 19], 1u);
        atomicAdd(&sh[__float_as_uint(k6) >> 19], 1u);
        atomicAdd(&sh[__float_as_uint(k7) >> 19], 1u);
    }
    __syncthreads();

    // suffix scan over descending buckets
    unsigned int v[8]; unsigned int s = 0;
    #pragma unroll
    for (int i = 0; i < 8; i++) { v[i] = sh[8191 - (t*8 + i)]; s += v[i]; }
    unsigned int x = s;
    int lane = t & 31, w = t >> 5;
    #pragma unroll
    for (int o = 1; o < 32; o <<= 1) {
        unsigned int y = __shfl_up_sync(0xffffffffu, x, o);
        if (lane >= o) x += y;
    }
    if (lane == 31) wsum[w] = x;
    __syncthreads();
    if (t < 32) {
        unsigned int y = wsum[t], z = y;
        #pragma unroll
        for (int o = 1; o < 32; o <<= 1) {
            unsigned int q = __shfl_up_sync(0xffffffffu, z, o);
            if (t >= o) z += q;
        }
        wsum[t] = z - y;                 // exclusive warp prefix
        if (t == 31) stot = z;
    }
    __syncthreads();
    unsigned int P = wsum[w] + x - s;    // samples strictly above this thread's chunk
    unsigned int K = (unsigned int)d_Kc[side];
    unsigned int sKt = K >> 3;
    unsigned int targHi = (sKt > SMARG) ? (sKt - SMARG) : 0u;
    unsigned int targLo = sKt + SMARG;
    unsigned int total = stot;
    unsigned int cum = P;
    #pragma unroll
    for (int i = 0; i < 8; i++) {
        int bb = 8191 - (t*8 + i);
        unsigned int hv = v[i];
        if (cum <= targHi && cum + hv > targHi) d_bHi[row] = bb;
        if (cum <  targLo && cum + hv >= targLo) d_bLo[row] = bb;
        cum += hv;
    }
    if (t == 0 && targLo > total) d_bLo[row] = 0;
}

// ---------------- k_mask: unroll x4, front-batched loads, aggregated append ----------------
extern __shared__ unsigned int mbuf[];
__global__ void __launch_bounds__(512, 2) k_mask(const float* __restrict__ u0s,
                                                 const float* __restrict__ u0t,
                                                 float* __restrict__ out)
{
    __shared__ float stab[112];
    __shared__ unsigned int s17[17];
    __shared__ unsigned int sCnt;
    unsigned int* bKey = mbuf;
    unsigned int* bIdx = mbuf + BUFCAP;

    int row   = blockIdx.x >> 3;
    int chunk = blockIdx.x & 7;
    int side  = row >> 5, b = row & 31;
    int t = threadIdx.x;
    if (t < 112) stab[t] = d_tab[side][b][t];
    if (t == 0) sCnt = 0u;
    __syncthreads();

    unsigned int bHi = (unsigned int)d_bHi[row];
    unsigned int bLo = (unsigned int)d_bLo[row];
    unsigned long long hk = ((unsigned long long)(bHi + 1)) << 19;
    float Thif = (hk >= 0x3F800000ull) ? 1.0f : __uint_as_float((unsigned int)hk);
    float Tlof = __uint_as_float(bLo << 19);

    const float4* src = (const float4*)((side ? u0t : u0s) + (size_t)b * NTOK);
    float4* out4 = (float4*)(out + (size_t)row * NTOK);
    unsigned int* segK = &d_candKey[row][chunk * CAPB];
    unsigned int* segI = &d_candIdx[row][chunk * CAPB];
    int lane = t & 31;
    unsigned int lmask = (1u << lane) - 1u;
    unsigned int nAbove = 0;
    unsigned int gTot = 0;               // uniform across block

    // per-thread invariants: strides (512, 16384) are multiples of 8 in float4 units
    int w0 = (t << 2) & 31;
    int h  = (t >> 3) & 31;
    float hC = stab[48 + h];
    float wj0 = stab[80+w0+0] * hC;
    float wj1 = stab[80+w0+1] * hC;
    float wj2 = stab[80+w0+2] * hC;
    float wj3 = stab[80+w0+3] * hC;

#define PROC(u, idx4) do {                                                          \
    float pre = stab[(idx4) >> 13] * stab[16 + (((idx4) >> 8) & 31)];               \
    float k0 = clampf((u).x) * pre * wj0;                                           \
    float k1 = clampf((u).y) * pre * wj1;                                           \
    float k2 = clampf((u).z) * pre * wj2;                                           \
    float k3 = clampf((u).w) * pre * wj3;                                           \
    bool a0 = (k0 >= Thif), a1 = (k1 >= Thif), a2 = (k2 >= Thif), a3 = (k3 >= Thif);\
    nAbove += (unsigned int)a0 + a1 + a2 + a3;                                      \
    unsigned int cm = (unsigned int)(!a0 && k0 >= Tlof)                             \
                    | ((unsigned int)(!a1 && k1 >= Tlof) << 1)                      \
                    | ((unsigned int)(!a2 && k2 >= Tlof) << 2)                      \
                    | ((unsigned int)(!a3 && k3 >= Tlof) << 3);                     \
    unsigned int b0 = __ballot_sync(0xffffffffu, cm & 1u);                          \
    unsigned int b1 = __ballot_sync(0xffffffffu, cm & 2u);                          \
    unsigned int b2 = __ballot_sync(0xffffffffu, cm & 4u);                          \
    unsigned int b3 = __ballot_sync(0xffffffffu, cm & 8u);                          \
    unsigned int c0 = __popc(b0), c1 = __popc(b1), c2 = __popc(b2), c3 = __popc(b3);\
    unsigned int tot = c0 + c1 + c2 + c3;                                           \
    if (tot) {                                                                      \
        unsigned int bp = 0;                                                        \
        if (lane == 0) bp = atomicAdd(&sCnt, tot);                                  \
        bp = __shfl_sync(0xffffffffu, bp, 0);                                       \
        int n = (idx4) << 2;                                                        \
        if (cm & 1u) { unsigned int p = bp + __popc(b0 & lmask);                    \
            if (p < BUFCAP) { bKey[p] = __float_as_uint(k0); bIdx[p] = (unsigned int)n; } } \
        if (cm & 2u) { unsigned int p = bp + c0 + __popc(b1 & lmask);               \
            if (p < BUFCAP) { bKey[p] = __float_as_uint(k1); bIdx[p] = (unsigned int)(n + 1); } } \
        if (cm & 4u) { unsigned int p = bp + c0 + c1 + __popc(b2 & lmask);          \
            if (p < BUFCAP) { bKey[p] = __float_as_uint(k2); bIdx[p] = (unsigned int)(n + 2); } } \
        if (cm & 8u) { unsigned int p = bp + c0 + c1 + c2 + __popc(b3 & lmask);     \
            if (p < BUFCAP) { bKey[p] = __float_as_uint(k3); bIdx[p] = (unsigned int)(n + 3); } } \
    }                                                                               \
    __stcs(&out4[(idx4)], make_float4(a0 ? 1.0f : 0.0f, a1 ? 1.0f : 0.0f,           \
                                      a2 ? 1.0f : 0.0f, a3 ? 1.0f : 0.0f));         \
} while (0)

    int base4 = chunk * 16384;
    for (int it = 0; it < 32; it += 4) {
        int i0 = base4 + it * 512 + t;
        int i1 = i0 + 512;
        int i2 = i0 + 1024;
        int i3 = i0 + 1536;
        // front-batched loads: MLP_p1 = 4
        float4 u0 = __ldcs(&src[i0]);
        float4 u1 = __ldcs(&src[i1]);
        float4 u2 = __ldcs(&src[i2]);
        float4 u3 = __ldcs(&src[i3]);
        PROC(u0, i0);
        PROC(u1, i1);
        PROC(u2, i2);
        PROC(u3, i3);

        // flush check every 4 iterations (max growth 4*512*4 = 8192)
        __syncthreads();
        unsigned int cur = sCnt;
        if (cur > BUFCAP - 8192u) {
            for (unsigned int i = t; i < cur; i += 512) {
                unsigned int gpos = gTot + i;
                if (gpos < CAPB) { segK[gpos] = bKey[i]; segI[gpos] = bIdx[i]; }
            }
            gTot += cur;
            __syncthreads();
            if (t == 0) sCnt = 0u;
            __syncthreads();
        }
    }
#undef PROC

    // final flush
    {
        unsigned int cur = sCnt;
        for (unsigned int i = t; i < cur; i += 512) {
            unsigned int gpos = gTot + i;
            if (gpos < CAPB) { segK[gpos] = bKey[i]; segI[gpos] = bIdx[i]; }
        }
        gTot += cur;
    }

    // above-count: block reduce, plain store per (row,chunk)
    unsigned int wv = __reduce_add_sync(0xffffffffu, nAbove);
    if (lane == 0) s17[t >> 5] = wv;
    __syncthreads();
    if (t < 16) {
        unsigned int z = s17[t];
        #pragma unroll
        for (int o = 8; o > 0; o >>= 1) z += __shfl_down_sync(0xffffu, z, o);
        if (t == 0) d_abovePart[row][chunk] = z;
    }
    if (t == 16) d_ccPart[row][chunk] = (gTot < CAPB) ? gTot : CAPB;
}

// ---------------- block reduce helper (fallback path only) ----------------
static __device__ __forceinline__ unsigned int blk_reduce_1024(unsigned int v, unsigned int* s33)
{
    unsigned int wv = __reduce_add_sync(0xffffffffu, v);
    int lane = threadIdx.x & 31, w = threadIdx.x >> 5;
    __syncthreads();
    if (lane == 0) s33[w] = wv;
    __syncthreads();
    if (threadIdx.x < 32) {
        unsigned int x = s33[threadIdx.x];
        x = __reduce_add_sync(0xffffffffu, x);
        if (threadIdx.x == 0) s33[32] = x;
    }
    __syncthreads();
    return s33[32];
}

// ---------------- k_select: radix-descent exact threshold + tie-break (8 segments) ----------------
extern __shared__ unsigned int selk[];
__global__ void __launch_bounds__(1024) k_select(float* __restrict__ out)
{
    __shared__ unsigned int hcnt[1024];
    __shared__ unsigned int wsum[32];
    __shared__ unsigned int sSel, sRnew;
    __shared__ unsigned int eqIdx[2048];
    __shared__ unsigned int eqCnt;
    __shared__ unsigned int sIstar;
    __shared__ unsigned int s33[33];

    int row = blockIdx.x, t = threadIdx.x;
    unsigned int cnt[NSEG], off[NSEG];
    unsigned int c = 0, above = 0;
    #pragma unroll
    for (int s = 0; s < NSEG; s++) {
        unsigned int cs = d_ccPart[row][s];
        cnt[s] = (cs < CAPB) ? cs : CAPB;
        off[s] = c;
        c += cnt[s];
        above += d_abovePart[row][s];
    }
    unsigned int K = (unsigned int)d_Kc[row >> 5];
    int R = (int)K - (int)above;
    const unsigned int* gk = d_candKey[row];
    const unsigned int* gi = d_candIdx[row];
    float* orow = out + (size_t)row * NTOK;
    if (R <= 0) return;
    if ((unsigned int)R >= c) {
        #pragma unroll
        for (int s = 0; s < NSEG; s++)
            for (unsigned int i = t; i < cnt[s]; i += 1024)
                orow[gi[s*CAPB + i]] = 1.0f;
        return;
    }

    bool insm = (c <= SELCAP);
    if (insm) {
        #pragma unroll
        for (int s = 0; s < NSEG; s++)
            for (unsigned int i = t; i < cnt[s]; i += 1024)
                selk[off[s] + i] = gk[s*CAPB + i];
        __syncthreads();
    }

    unsigned int bLo = (unsigned int)d_bLo[row], bHi = (unsigned int)d_bHi[row];
    unsigned int base = bLo << 19;
    unsigned long long Wd = ((unsigned long long)(bHi + 1u - bLo)) << 19;
    int sb = (Wd <= 1ull) ? 0 : (64 - __clzll(Wd - 1ull));
    if (sb > 32) sb = 32;
    unsigned int Rcur = (unsigned int)R;

    while (sb > 0) {
        int bits = sb >= 10 ? 10 : sb;
        int shift = sb - bits;
        hcnt[t] = 0u;
        __syncthreads();
        unsigned int spanm = (sb >= 32) ? 0xFFFFFFFFu : ((1u << sb) - 1u);
        if (insm) {
            for (unsigned int i = t; i < c; i += 1024) {
                unsigned int k = selk[i];
                unsigned int d = k - base;
                if (k >= base && d <= spanm) atomicAdd(&hcnt[d >> shift], 1u);
            }
        } else {
            #pragma unroll
            for (int s = 0; s < NSEG; s++)
                for (unsigned int i = t; i < cnt[s]; i += 1024) {
                    unsigned int k = gk[s*CAPB + i];
                    unsigned int d = k - base;
                    if (k >= base && d <= spanm) atomicAdd(&hcnt[d >> shift], 1u);
                }
        }
        __syncthreads();
        unsigned int x = hcnt[1023 - t];
        unsigned int cb = x;
        int lane = t & 31, w = t >> 5;
        #pragma unroll
        for (int o = 1; o < 32; o <<= 1) {
            unsigned int y = __shfl_up_sync(0xffffffffu, x, o);
            if (lane >= o) x += y;
        }
        if (lane == 31) wsum[w] = x;
        __syncthreads();
        if (t < 32) {
            unsigned int y = wsum[t], z = y;
            #pragma unroll
            for (int o = 1; o < 32; o <<= 1) {
                unsigned int q = __shfl_up_sync(0xffffffffu, z, o);
                if (t >= o) z += q;
            }
            wsum[t] = z - y;
        }
        __syncthreads();
        unsigned int incl = wsum[w] + x;
        unsigned int A = incl - cb;
        if (A < Rcur && Rcur <= incl) { sSel = (unsigned int)(1023 - t); sRnew = Rcur - A; }
        __syncthreads();
        base += sSel << shift;
        Rcur = sRnew;
        sb = shift;
        __syncthreads();
    }
    unsigned int Tkey = base;
    unsigned int R3 = Rcur;   // rank among equal keys (stable by index), >= 1

    if (t == 0) eqCnt = 0u;
    __syncthreads();
    #pragma unroll
    for (int s = 0; s < NSEG; s++)
        for (unsigned int i = t; i < cnt[s]; i += 1024) {
            unsigned int k = insm ? selk[off[s] + i] : gk[s*CAPB + i];
            if (k == Tkey) {
                unsigned int p = atomicAdd(&eqCnt, 1u);
                if (p < 2048) eqIdx[p] = gi[s*CAPB + i];
            }
        }
    __syncthreads();
    unsigned int e = eqCnt;
    unsigned int Istar;
    if (e <= 2048) {
        for (unsigned int j = t; j < e; j += 1024) {
            unsigned int my = eqIdx[j], r = 0;
            for (unsigned int m = 0; m < e; m++) r += (eqIdx[m] < my);
            if (r == R3 - 1u) sIstar = my;
        }
        __syncthreads();
        Istar = sIstar;
    } else {
        unsigned int ilo = 0, ihi = NTOK - 1;
        while (ilo < ihi) {
            unsigned int mid = (ilo + ihi) >> 1;
            unsigned int l2 = 0;
            #pragma unroll
            for (int s = 0; s < NSEG; s++)
                for (unsigned int i = t; i < cnt[s]; i += 1024) {
                    unsigned int k = insm ? selk[off[s] + i] : gk[s*CAPB + i];
                    if (k == Tkey) l2 += (gi[s*CAPB + i] <= mid);
                }
            unsigned int cc2 = blk_reduce_1024(l2, s33);
            if (cc2 >= R3) ihi = mid; else ilo = mid + 1u;
        }
        Istar = ilo;
    }

    #pragma unroll
    for (int s = 0; s < NSEG; s++)
        for (unsigned int i = t; i < cnt[s]; i += 1024) {
            unsigned int k = insm ? selk[off[s] + i] : gk[s*CAPB + i];
            if (k > Tkey || (k == Tkey && gi[s*CAPB + i] <= Istar))
                orow[gi[s*CAPB + i]] = 1.0f;
        }
}

// ---------------- launch ----------------
extern "C" void kernel_launch(void* const* d_in, const int* in_sizes, int n_in,
                              void* d_out, int out_size)
{
    const float* comps = (const float*)d_in[0];
    const float* ur_s  = (const float*)d_in[1];
    const float* ur_t  = (const float*)d_in[2];
    const float* u0s   = (const float*)d_in[3];
    const float* u0t   = (const float*)d_in[4];
    const float* uv_s  = (const float*)d_in[5];
    const float* ut_s  = (const float*)d_in[6];
    const float* uh_s  = (const float*)d_in[7];
    const float* uw_s  = (const float*)d_in[8];
    const float* uv_t  = (const float*)d_in[9];
    const float* ut_t  = (const float*)d_in[10];
    const float* uh_t  = (const float*)d_in[11];
    const float* uw_t  = (const float*)d_in[12];
    const int*   idx   = (const int*)d_in[13];
    float* out = (float*)d_out;

    static int attr_done = 0;
    if (!attr_done) {
        cudaFuncSetAttribute(k_mask, cudaFuncAttributeMaxDynamicSharedMemorySize,
                             BUFCAP * 2 * sizeof(unsigned int));
        cudaFuncSetAttribute(k_select, cudaFuncAttributeMaxDynamicSharedMemorySize,
                             SELCAP * sizeof(unsigned int));
        attr_done = 1;
    }

    k_init<<<1, 256>>>(comps, idx, ur_s, ur_t,
                       uv_s, ut_s, uh_s, uw_s,
                       uv_t, ut_t, uh_t, uw_t);
    k_histscan<<<64, 1024>>>(u0s, u0t);
    k_mask<<<512, 512, BUFCAP * 2 * sizeof(unsigned int)>>>(u0s, u0t, out);
    k_select<<<64, 1024, SELCAP * sizeof(unsigned int)>>>(out);
}

// round 9
// speedup vs baseline: 1.4722x; 1.2006x over previous
#include <cuda_runtime.h>
#include <cstdint>

#define NTOK   524288     // 16*32*32*32
#define BATCH  32
#define ROWS   64         // 2 sides * 32 batch
#define NB1    8192       // buckets: float bits >> 19
#define SMARG  1024u      // sample-rank margin (true ranks: *8)
#define NSEG   8          // candidate segments per row (= k_mask chunks)
#define CAPB   8192       // per-segment candidate capacity
#define BUFCAP 12288      // per-block smem candidate buffer
#define SELC   24576      // smem-resident (key+idx) cap in k_select

static __device__ __forceinline__ float clampf(float x) {
    return fminf(fmaxf(x, 1e-3f), 0.999f);
}

// ---------------- scratch ----------------
__device__ float        d_tab[2][BATCH][112];         // Ev[16] Et[32] Eh[32] Ew[32]
__device__ int          d_Kc[2];
__device__ int          d_bHi[ROWS];
__device__ int          d_bLo[ROWS];
__device__ unsigned int d_abovePart[ROWS][NSEG];
__device__ unsigned int d_ccPart[ROWS][NSEG];
__device__ unsigned int d_candKey[ROWS][NSEG * CAPB]; // 16 MB
__device__ unsigned int d_candIdx[ROWS][NSEG * CAPB]; // 16 MB

// ---------------- k_histscan: tables + sampled hist (1/8) + suffix scan, 1 block/row ----------------
__global__ void __launch_bounds__(1024) k_histscan(
    const float* __restrict__ comps, const int* __restrict__ idxp,
    const float* __restrict__ ur_s, const float* __restrict__ ur_t,
    const float* __restrict__ uv_s, const float* __restrict__ ut_s,
    const float* __restrict__ uh_s, const float* __restrict__ uw_s,
    const float* __restrict__ uv_t, const float* __restrict__ ut_t,
    const float* __restrict__ uh_t, const float* __restrict__ uw_t,
    const float* __restrict__ u0s, const float* __restrict__ u0t)
{
    __shared__ unsigned int sh[NB1];
    __shared__ float stab[112];
    __shared__ unsigned int wsum[32];
    __shared__ unsigned int stot;
    int row  = blockIdx.x;
    int side = row >> 5, b = row & 31;
    int t = threadIdx.x;
    for (int i = t; i < NB1; i += 1024) sh[i] = 0u;

    // compute this row's pow-table (also publish for k_mask)
    if (t < 112) {
        int id = idxp[0];
        const float* uv = side ? uv_t : uv_s;
        const float* ut = side ? ut_t : ut_s;
        const float* uh = side ? uh_t : uh_s;
        const float* uw = side ? uw_t : uw_s;
        float val, ia;
        if (t < 16)      { val = uv[b*16 +  t     ]; ia = 1.0f / comps[id*4+0]; }
        else if (t < 48) { val = ut[b*32 + (t-16)]; ia = 1.0f / comps[id*4+1]; }
        else if (t < 80) { val = uh[b*32 + (t-48)]; ia = 1.0f / comps[id*4+2]; }
        else             { val = uw[b*32 + (t-80)]; ia = 1.0f / comps[id*4+3]; }
        float e = powf(clampf(val), ia);
        stab[t] = e;
        d_tab[side][b][t] = e;
    }
    if (row == 0 && t == 0) d_Kc[0] = (int)(clampf(ur_s[0]) * (float)NTOK);
    if (row == 0 && t == 1) d_Kc[1] = (int)(clampf(ur_t[0]) * (float)NTOK);
    __syncthreads();

    const float4* src = (const float4*)((side ? u0t : u0s) + (size_t)b * NTOK);

    // 2048 groups of 32 consecutive tokens; 8 passes of 256 groups
    for (int ch = 0; ch < 8; ch++) {
        int g  = ch * 256 + (t >> 2);
        int q  = t & 3;
        int v  = g >> 7;
        int tt = (g >> 2) & 31;
        int j  = g & 3;
        int h  = (v*3 + tt*5 + j*8) & 31;
        float pre = stab[v] * stab[16+tt] * stab[48+h];
        int base4 = ((((v << 5) | tt) << 5) | h) * 8 + q * 2;
        int w = q * 8;

        float4 a = src[base4];
        float4 c = src[base4 + 1];
        float k0 = clampf(a.x) * pre * stab[80+w+0];
        float k1 = clampf(a.y) * pre * stab[80+w+1];
        float k2 = clampf(a.z) * pre * stab[80+w+2];
        float k3 = clampf(a.w) * pre * stab[80+w+3];
        float k4 = clampf(c.x) * pre * stab[80+w+4];
        float k5 = clampf(c.y) * pre * stab[80+w+5];
        float k6 = clampf(c.z) * pre * stab[80+w+6];
        float k7 = clampf(c.w) * pre * stab[80+w+7];
        atomicAdd(&sh[__float_as_uint(k0) >> 19], 1u);
        atomicAdd(&sh[__float_as_uint(k1) >> 19], 1u);
        atomicAdd(&sh[__float_as_uint(k2) >> 19], 1u);
        atomicAdd(&sh[__float_as_uint(k3) >> 19], 1u);
        atomicAdd(&sh[__float_as_uint(k4) >> 19], 1u);
        atomicAdd(&sh[__float_as_uint(k5) >> 19], 1u);
        atomicAdd(&sh[__float_as_uint(k6) >> 19], 1u);
        atomicAdd(&sh[__float_as_uint(k7) >> 19], 1u);
    }
    __syncthreads();

    // suffix scan over descending buckets
    unsigned int v[8]; unsigned int s = 0;
    #pragma unroll
    for (int i = 0; i < 8; i++) { v[i] = sh[8191 - (t*8 + i)]; s += v[i]; }
    unsigned int x = s;
    int lane = t & 31, w = t >> 5;
    #pragma unroll
    for (int o = 1; o < 32; o <<= 1) {
        unsigned int y = __shfl_up_sync(0xffffffffu, x, o);
        if (lane >= o) x += y;
    }
    if (lane == 31) wsum[w] = x;
    __syncthreads();
    if (t < 32) {
        unsigned int y = wsum[t], z = y;
        #pragma unroll
        for (int o = 1; o < 32; o <<= 1) {
            unsigned int q = __shfl_up_sync(0xffffffffu, z, o);
            if (t >= o) z += q;
        }
        wsum[t] = z - y;                 // exclusive warp prefix
        if (t == 31) stot = z;
    }
    __syncthreads();
    unsigned int P = wsum[w] + x - s;    // samples strictly above this thread's chunk
    float urv = side ? ur_t[0] : ur_s[0];
    unsigned int K = (unsigned int)(int)(clampf(urv) * (float)NTOK);
    unsigned int sKt = K >> 3;
    unsigned int targHi = (sKt > SMARG) ? (sKt - SMARG) : 0u;
    unsigned int targLo = sKt + SMARG;
    unsigned int total = stot;
    unsigned int cum = P;
    #pragma unroll
    for (int i = 0; i < 8; i++) {
        int bb = 8191 - (t*8 + i);
        unsigned int hv = v[i];
        if (cum <= targHi && cum + hv > targHi) d_bHi[row] = bb;
        if (cum <  targLo && cum + hv >= targLo) d_bLo[row] = bb;
        cum += hv;
    }
    if (t == 0 && targLo > total) d_bLo[row] = 0;
}

// ---------------- k_mask: unroll x4, front-batched loads, aggregated append ----------------
extern __shared__ unsigned int mbuf[];
__global__ void __launch_bounds__(512, 2) k_mask(const float* __restrict__ u0s,
                                                 const float* __restrict__ u0t,
                                                 float* __restrict__ out)
{
    __shared__ float stab[112];
    __shared__ unsigned int s17[17];
    __shared__ unsigned int sCnt;
    unsigned int* bKey = mbuf;
    unsigned int* bIdx = mbuf + BUFCAP;

    int row   = blockIdx.x >> 3;
    int chunk = blockIdx.x & 7;
    int side  = row >> 5, b = row & 31;
    int t = threadIdx.x;
    if (t < 112) stab[t] = d_tab[side][b][t];
    if (t == 0) sCnt = 0u;
    __syncthreads();

    unsigned int bHi = (unsigned int)d_bHi[row];
    unsigned int bLo = (unsigned int)d_bLo[row];
    unsigned long long hk = ((unsigned long long)(bHi + 1)) << 19;
    float Thif = (hk >= 0x3F800000ull) ? 1.0f : __uint_as_float((unsigned int)hk);
    float Tlof = __uint_as_float(bLo << 19);

    const float4* src = (const float4*)((side ? u0t : u0s) + (size_t)b * NTOK);
    float4* out4 = (float4*)(out + (size_t)row * NTOK);
    unsigned int* segK = &d_candKey[row][chunk * CAPB];
    unsigned int* segI = &d_candIdx[row][chunk * CAPB];
    int lane = t & 31;
    unsigned int lmask = (1u << lane) - 1u;
    unsigned int nAbove = 0;
    unsigned int gTot = 0;               // uniform across block

    int w0 = (t << 2) & 31;
    int h  = (t >> 3) & 31;
    float hC = stab[48 + h];
    float wj0 = stab[80+w0+0] * hC;
    float wj1 = stab[80+w0+1] * hC;
    float wj2 = stab[80+w0+2] * hC;
    float wj3 = stab[80+w0+3] * hC;

#define PROC(u, idx4) do {                                                          \
    float pre = stab[(idx4) >> 13] * stab[16 + (((idx4) >> 8) & 31)];               \
    float k0 = clampf((u).x) * pre * wj0;                                           \
    float k1 = clampf((u).y) * pre * wj1;                                           \
    float k2 = clampf((u).z) * pre * wj2;                                           \
    float k3 = clampf((u).w) * pre * wj3;                                           \
    bool a0 = (k0 >= Thif), a1 = (k1 >= Thif), a2 = (k2 >= Thif), a3 = (k3 >= Thif);\
    nAbove += (unsigned int)a0 + a1 + a2 + a3;                                      \
    unsigned int cm = (unsigned int)(!a0 && k0 >= Tlof)                             \
                    | ((unsigned int)(!a1 && k1 >= Tlof) << 1)                      \
                    | ((unsigned int)(!a2 && k2 >= Tlof) << 2)                      \
                    | ((unsigned int)(!a3 && k3 >= Tlof) << 3);                     \
    unsigned int b0 = __ballot_sync(0xffffffffu, cm & 1u);                          \
    unsigned int b1 = __ballot_sync(0xffffffffu, cm & 2u);                          \
    unsigned int b2 = __ballot_sync(0xffffffffu, cm & 4u);                          \
    unsigned int b3 = __ballot_sync(0xffffffffu, cm & 8u);                          \
    unsigned int c0 = __popc(b0), c1 = __popc(b1), c2 = __popc(b2), c3 = __popc(b3);\
    unsigned int tot = c0 + c1 + c2 + c3;                                           \
    if (tot) {                                                                      \
        unsigned int bp = 0;                                                        \
        if (lane == 0) bp = atomicAdd(&sCnt, tot);                                  \
        bp = __shfl_sync(0xffffffffu, bp, 0);                                       \
        int n = (idx4) << 2;                                                        \
        if (cm & 1u) { unsigned int p = bp + __popc(b0 & lmask);                    \
            if (p < BUFCAP) { bKey[p] = __float_as_uint(k0); bIdx[p] = (unsigned int)n; } } \
        if (cm & 2u) { unsigned int p = bp + c0 + __popc(b1 & lmask);               \
            if (p < BUFCAP) { bKey[p] = __float_as_uint(k1); bIdx[p] = (unsigned int)(n + 1); } } \
        if (cm & 4u) { unsigned int p = bp + c0 + c1 + __popc(b2 & lmask);          \
            if (p < BUFCAP) { bKey[p] = __float_as_uint(k2); bIdx[p] = (unsigned int)(n + 2); } } \
        if (cm & 8u) { unsigned int p = bp + c0 + c1 + c2 + __popc(b3 & lmask);     \
            if (p < BUFCAP) { bKey[p] = __float_as_uint(k3); bIdx[p] = (unsigned int)(n + 3); } } \
    }                                                                               \
    __stcs(&out4[(idx4)], make_float4(a0 ? 1.0f : 0.0f, a1 ? 1.0f : 0.0f,           \
                                      a2 ? 1.0f : 0.0f, a3 ? 1.0f : 0.0f));         \
} while (0)

    int base4 = chunk * 16384;
    for (int it = 0; it < 32; it += 4) {
        int i0 = base4 + it * 512 + t;
        int i1 = i0 + 512;
        int i2 = i0 + 1024;
        int i3 = i0 + 1536;
        float4 u0 = __ldcs(&src[i0]);
        float4 u1 = __ldcs(&src[i1]);
        float4 u2 = __ldcs(&src[i2]);
        float4 u3 = __ldcs(&src[i3]);
        PROC(u0, i0);
        PROC(u1, i1);
        PROC(u2, i2);
        PROC(u3, i3);

        __syncthreads();
        unsigned int cur = sCnt;
        if (cur > BUFCAP - 8192u) {
            for (unsigned int i = t; i < cur; i += 512) {
                unsigned int gpos = gTot + i;
                if (gpos < CAPB) { segK[gpos] = bKey[i]; segI[gpos] = bIdx[i]; }
            }
            gTot += cur;
            __syncthreads();
            if (t == 0) sCnt = 0u;
            __syncthreads();
        }
    }
#undef PROC

    {
        unsigned int cur = sCnt;
        for (unsigned int i = t; i < cur; i += 512) {
            unsigned int gpos = gTot + i;
            if (gpos < CAPB) { segK[gpos] = bKey[i]; segI[gpos] = bIdx[i]; }
        }
        gTot += cur;
    }

    unsigned int wv = __reduce_add_sync(0xffffffffu, nAbove);
    if (lane == 0) s17[t >> 5] = wv;
    __syncthreads();
    if (t < 16) {
        unsigned int z = s17[t];
        #pragma unroll
        for (int o = 8; o > 0; o >>= 1) z += __shfl_down_sync(0xffffu, z, o);
        if (t == 0) d_abovePart[row][chunk] = z;
    }
    if (t == 16) d_ccPart[row][chunk] = (gTot < CAPB) ? gTot : CAPB;
}

// ---------------- block reduce helper (fallback path only) ----------------
static __device__ __forceinline__ unsigned int blk_reduce_1024(unsigned int v, unsigned int* s33)
{
    unsigned int wv = __reduce_add_sync(0xffffffffu, v);
    int lane = threadIdx.x & 31, w = threadIdx.x >> 5;
    __syncthreads();
    if (lane == 0) s33[w] = wv;
    __syncthreads();
    if (threadIdx.x < 32) {
        unsigned int x = s33[threadIdx.x];
        x = __reduce_add_sync(0xffffffffu, x);
        if (threadIdx.x == 0) s33[32] = x;
    }
    __syncthreads();
    return s33[32];
}

// ---------------- k_select: smem-resident keys+idx, radix descent + tie-break ----------------
extern __shared__ unsigned int dynsm[];
__global__ void __launch_bounds__(1024) k_select(float* __restrict__ out)
{
    __shared__ unsigned int hcnt[1024];
    __shared__ unsigned int wsum[32];
    __shared__ unsigned int sSel, sRnew;
    __shared__ unsigned int eqIdx[2048];
    __shared__ unsigned int eqCnt;
    __shared__ unsigned int sIstar;
    __shared__ unsigned int s33[33];
    unsigned int* keys = dynsm;
    unsigned int* idxs = dynsm + SELC;

    int row = blockIdx.x, t = threadIdx.x;
    unsigned int cnt[NSEG], off[NSEG];
    unsigned int c = 0, above = 0;
    #pragma unroll
    for (int s = 0; s < NSEG; s++) {
        unsigned int cs = d_ccPart[row][s];
        cnt[s] = (cs < CAPB) ? cs : CAPB;
        off[s] = c;
        c += cnt[s];
        above += d_abovePart[row][s];
    }
    unsigned int K = (unsigned int)d_Kc[row >> 5];
    int R = (int)K - (int)above;
    const unsigned int* gk = d_candKey[row];
    const unsigned int* gi = d_candIdx[row];
    float* orow = out + (size_t)row * NTOK;
    if (R <= 0) return;
    if ((unsigned int)R >= c) {
        #pragma unroll
        for (int s = 0; s < NSEG; s++)
            for (unsigned int i = t; i < cnt[s]; i += 1024)
                orow[gi[s*CAPB + i]] = 1.0f;
        return;
    }

    bool insm = (c <= SELC);
    if (insm) {
        #pragma unroll
        for (int s = 0; s < NSEG; s++)
            for (unsigned int i = t; i < cnt[s]; i += 1024) {
                keys[off[s] + i] = gk[s*CAPB + i];
                idxs[off[s] + i] = gi[s*CAPB + i];
            }
        __syncthreads();
    }

    unsigned int bLo = (unsigned int)d_bLo[row], bHi = (unsigned int)d_bHi[row];
    unsigned int base = bLo << 19;
    unsigned long long Wd = ((unsigned long long)(bHi + 1u - bLo)) << 19;
    int sb = (Wd <= 1ull) ? 0 : (64 - __clzll(Wd - 1ull));
    if (sb > 32) sb = 32;
    unsigned int Rcur = (unsigned int)R;

    while (sb > 0) {
        int bits = sb >= 10 ? 10 : sb;
        int shift = sb - bits;
        hcnt[t] = 0u;
        __syncthreads();
        unsigned int spanm = (sb >= 32) ? 0xFFFFFFFFu : ((1u << sb) - 1u);
        if (insm) {
            for (unsigned int i = t; i < c; i += 1024) {
                unsigned int k = keys[i];
                unsigned int d = k - base;
                if (k >= base && d <= spanm) atomicAdd(&hcnt[d >> shift], 1u);
            }
        } else {
            #pragma unroll
            for (int s = 0; s < NSEG; s++)
                for (unsigned int i = t; i < cnt[s]; i += 1024) {
                    unsigned int k = gk[s*CAPB + i];
                    unsigned int d = k - base;
                    if (k >= base && d <= spanm) atomicAdd(&hcnt[d >> shift], 1u);
                }
        }
        __syncthreads();
        unsigned int x = hcnt[1023 - t];
        unsigned int cb = x;
        int lane = t & 31, w = t >> 5;
        #pragma unroll
        for (int o = 1; o < 32; o <<= 1) {
            unsigned int y = __shfl_up_sync(0xffffffffu, x, o);
            if (lane >= o) x += y;
        }
        if (lane == 31) wsum[w] = x;
        __syncthreads();
        if (t < 32) {
            unsigned int y = wsum[t], z = y;
            #pragma unroll
            for (int o = 1; o < 32; o <<= 1) {
                unsigned int q = __shfl_up_sync(0xffffffffu, z, o);
                if (t >= o) z += q;
            }
            wsum[t] = z - y;
        }
        __syncthreads();
        unsigned int incl = wsum[w] + x;
        unsigned int A = incl - cb;
        if (A < Rcur && Rcur <= incl) { sSel = (unsigned int)(1023 - t); sRnew = Rcur - A; }
        __syncthreads();
        base += sSel << shift;
        Rcur = sRnew;
        sb = shift;
        __syncthreads();
    }
    unsigned int Tkey = base;
    unsigned int R3 = Rcur;   // rank among equal keys (stable by index), >= 1

    if (t == 0) eqCnt = 0u;
    __syncthreads();
    if (insm) {
        for (unsigned int i = t; i < c; i += 1024)
            if (keys[i] == Tkey) {
                unsigned int p = atomicAdd(&eqCnt, 1u);
                if (p < 2048) eqIdx[p] = idxs[i];
            }
    } else {
        #pragma unroll
        for (int s = 0; s < NSEG; s++)
            for (unsigned int i = t; i < cnt[s]; i += 1024)
                if (gk[s*CAPB + i] == Tkey) {
                    unsigned int p = atomicAdd(&eqCnt, 1u);
                    if (p < 2048) eqIdx[p] = gi[s*CAPB + i];
                }
    }
    __syncthreads();
    unsigned int e = eqCnt;
    unsigned int Istar;
    if (e <= 2048) {
        for (unsigned int j = t; j < e; j += 1024) {
            unsigned int my = eqIdx[j], r = 0;
            for (unsigned int m = 0; m < e; m++) r += (eqIdx[m] < my);
            if (r == R3 - 1u) sIstar = my;
        }
        __syncthreads();
        Istar = sIstar;
    } else {
        unsigned int ilo = 0, ihi = NTOK - 1;
        while (ilo < ihi) {
            unsigned int mid = (ilo + ihi) >> 1;
            unsigned int l2 = 0;
            if (insm) {
                for (unsigned int i = t; i < c; i += 1024)
                    if (keys[i] == Tkey) l2 += (idxs[i] <= mid);
            } else {
                #pragma unroll
                for (int s = 0; s < NSEG; s++)
                    for (unsigned int i = t; i < cnt[s]; i += 1024)
                        if (gk[s*CAPB + i] == Tkey) l2 += (gi[s*CAPB + i] <= mid);
            }
            unsigned int cc2 = blk_reduce_1024(l2, s33);
            if (cc2 >= R3) ihi = mid; else ilo = mid + 1u;
        }
        Istar = ilo;
    }

    if (insm) {
        for (unsigned int i = t; i < c; i += 1024) {
            unsigned int k = keys[i];
            if (k > Tkey || (k == Tkey && idxs[i] <= Istar)) orow[idxs[i]] = 1.0f;
        }
    } else {
        #pragma unroll
        for (int s = 0; s < NSEG; s++)
            for (unsigned int i = t; i < cnt[s]; i += 1024) {
                unsigned int k = gk[s*CAPB + i];
                if (k > Tkey || (k == Tkey && gi[s*CAPB + i] <= Istar))
                    orow[gi[s*CAPB + i]] = 1.0f;
            }
    }
}

// ---------------- launch ----------------
extern "C" void kernel_launch(void* const* d_in, const int* in_sizes, int n_in,
                              void* d_out, int out_size)
{
    const float* comps = (const float*)d_in[0];
    const float* ur_s  = (const float*)d_in[1];
    const float* ur_t  = (const float*)d_in[2];
    const float* u0s   = (const float*)d_in[3];
    const float* u0t   = (const float*)d_in[4];
    const float* uv_s  = (const float*)d_in[5];
    const float* ut_s  = (const float*)d_in[6];
    const float* uh_s  = (const float*)d_in[7];
    const float* uw_s  = (const float*)d_in[8];
    const float* uv_t  = (const float*)d_in[9];
    const float* ut_t  = (const float*)d_in[10];
    const float* uh_t  = (const float*)d_in[11];
    const float* uw_t  = (const float*)d_in[12];
    const int*   idx   = (const int*)d_in[13];
    float* out = (float*)d_out;

    static int attr_done = 0;
    if (!attr_done) {
        cudaFuncSetAttribute(k_mask, cudaFuncAttributeMaxDynamicSharedMemorySize,
                             BUFCAP * 2 * sizeof(unsigned int));
        cudaFuncSetAttribute(k_select, cudaFuncAttributeMaxDynamicSharedMemorySize,
                             SELC * 2 * sizeof(unsigned int));
        attr_done = 1;
    }

    k_histscan<<<64, 1024>>>(comps, idx, ur_s, ur_t,
                             uv_s, ut_s, uh_s, uw_s,
                             uv_t, ut_t, uh_t, uw_t,
                             u0s, u0t);
    k_mask<<<512, 512, BUFCAP * 2 * sizeof(unsigned int)>>>(u0s, u0t, out);
    k_select<<<64, 1024, SELC * 2 * sizeof(unsigned int)>>>(out);
}

// round 10
// speedup vs baseline: 1.5855x; 1.0770x over previous
#include <cuda_runtime.h>
#include <cstdint>

#define NTOK   524288     // 16*32*32*32
#define BATCH  32
#define ROWS   64         // 2 sides * 32 batch
#define NB1    8192       // buckets: float bits >> 19
#define SMARG  1024u      // sample-rank margin (true ranks: *8)
#define NSEG   8          // candidate segments per row (= k_mask chunks)
#define CAPB   8192       // per-segment candidate capacity
#define BUFCAP 12288      // per-block smem candidate buffer
#define SELC   24576      // smem-resident (key+idx) cap in k_select

static __device__ __forceinline__ float clampf(float x) {
    return fminf(fmaxf(x, 1e-3f), 0.999f);
}

// ---------------- scratch ----------------
__device__ float        d_tab[2][BATCH][112];         // Ev[16] Et[32] Eh[32] Ew[32]
__device__ int          d_Kc[2];
__device__ int          d_bHi[ROWS];
__device__ int          d_bLo[ROWS];
__device__ unsigned int d_abovePart[ROWS][NSEG];
__device__ unsigned int d_ccPart[ROWS][NSEG];
__device__ unsigned int d_candKey[ROWS][NSEG * CAPB]; // 16 MB
__device__ unsigned int d_candIdx[ROWS][NSEG * CAPB]; // 16 MB

// ---------------- k_histscan: tables + sampled hist (1/8) + suffix scan, 1 block/row ----------------
__global__ void __launch_bounds__(1024) k_histscan(
    const float* __restrict__ comps, const int* __restrict__ idxp,
    const float* __restrict__ ur_s, const float* __restrict__ ur_t,
    const float* __restrict__ uv_s, const float* __restrict__ ut_s,
    const float* __restrict__ uh_s, const float* __restrict__ uw_s,
    const float* __restrict__ uv_t, const float* __restrict__ ut_t,
    const float* __restrict__ uh_t, const float* __restrict__ uw_t,
    const float* __restrict__ u0s, const float* __restrict__ u0t)
{
    __shared__ unsigned int sh[NB1];
    __shared__ float stab[112];
    __shared__ unsigned int wsum[32];
    __shared__ unsigned int stot;
    int row  = blockIdx.x;
    int side = row >> 5, b = row & 31;
    int t = threadIdx.x;
    for (int i = t; i < NB1; i += 1024) sh[i] = 0u;

    // compute this row's pow-table (also publish for k_mask)
    if (t < 112) {
        int id = idxp[0];
        const float* uv = side ? uv_t : uv_s;
        const float* ut = side ? ut_t : ut_s;
        const float* uh = side ? uh_t : uh_s;
        const float* uw = side ? uw_t : uw_s;
        float val, ia;
        if (t < 16)      { val = uv[b*16 +  t     ]; ia = 1.0f / comps[id*4+0]; }
        else if (t < 48) { val = ut[b*32 + (t-16)]; ia = 1.0f / comps[id*4+1]; }
        else if (t < 80) { val = uh[b*32 + (t-48)]; ia = 1.0f / comps[id*4+2]; }
        else             { val = uw[b*32 + (t-80)]; ia = 1.0f / comps[id*4+3]; }
        float e = powf(clampf(val), ia);
        stab[t] = e;
        d_tab[side][b][t] = e;
    }
    if (row == 0 && t == 0) d_Kc[0] = (int)(clampf(ur_s[0]) * (float)NTOK);
    if (row == 0 && t == 1) d_Kc[1] = (int)(clampf(ur_t[0]) * (float)NTOK);
    __syncthreads();

    const float4* src = (const float4*)((side ? u0t : u0s) + (size_t)b * NTOK);

    // group geometry per chunk: g = ch*256 + (t>>2), q = t&3
    int q  = t & 3;
    int w  = q * 8;

    // prologue: load chunk 0
    int g0  = (t >> 2);
    int v0  = g0 >> 7, tt0 = (g0 >> 2) & 31, j0 = g0 & 3;
    int h0  = (v0*3 + tt0*5 + j0*8) & 31;
    int b40 = ((((v0 << 5) | tt0) << 5) | h0) * 8 + q * 2;
    float4 A = src[b40];
    float4 C = src[b40 + 1];
    float preCur = stab[v0] * stab[16+tt0] * stab[48+h0];

    for (int ch = 0; ch < 8; ch++) {
        // prefetch next chunk before doing this chunk's atomics
        float4 A2, C2;
        float preNext = 0.0f;
        if (ch < 7) {
            int g  = (ch + 1) * 256 + (t >> 2);
            int v  = g >> 7, tt = (g >> 2) & 31, j = g & 3;
            int h  = (v*3 + tt*5 + j*8) & 31;
            int b4 = ((((v << 5) | tt) << 5) | h) * 8 + q * 2;
            A2 = src[b4];
            C2 = src[b4 + 1];
            preNext = stab[v] * stab[16+tt] * stab[48+h];
        }

        float pre = preCur;
        float k0 = clampf(A.x) * pre * stab[80+w+0];
        float k1 = clampf(A.y) * pre * stab[80+w+1];
        float k2 = clampf(A.z) * pre * stab[80+w+2];
        float k3 = clampf(A.w) * pre * stab[80+w+3];
        float k4 = clampf(C.x) * pre * stab[80+w+4];
        float k5 = clampf(C.y) * pre * stab[80+w+5];
        float k6 = clampf(C.z) * pre * stab[80+w+6];
        float k7 = clampf(C.w) * pre * stab[80+w+7];
        atomicAdd(&sh[__float_as_uint(k0) >> 19], 1u);
        atomicAdd(&sh[__float_as_uint(k1) >> 19], 1u);
        atomicAdd(&sh[__float_as_uint(k2) >> 19], 1u);
        atomicAdd(&sh[__float_as_uint(k3) >> 19], 1u);
        atomicAdd(&sh[__float_as_uint(k4) >> 19], 1u);
        atomicAdd(&sh[__float_as_uint(k5) >> 19], 1u);
        atomicAdd(&sh[__float_as_uint(k6) >> 19], 1u);
        atomicAdd(&sh[__float_as_uint(k7) >> 19], 1u);

        A = A2; C = C2; preCur = preNext;
    }
    __syncthreads();

    // suffix scan over descending buckets
    unsigned int v[8]; unsigned int s = 0;
    #pragma unroll
    for (int i = 0; i < 8; i++) { v[i] = sh[8191 - (t*8 + i)]; s += v[i]; }
    unsigned int x = s;
    int lane = t & 31, wp = t >> 5;
    #pragma unroll
    for (int o = 1; o < 32; o <<= 1) {
        unsigned int y = __shfl_up_sync(0xffffffffu, x, o);
        if (lane >= o) x += y;
    }
    if (lane == 31) wsum[wp] = x;
    __syncthreads();
    if (t < 32) {
        unsigned int y = wsum[t], z = y;
        #pragma unroll
        for (int o = 1; o < 32; o <<= 1) {
            unsigned int qq = __shfl_up_sync(0xffffffffu, z, o);
            if (t >= o) z += qq;
        }
        wsum[t] = z - y;                 // exclusive warp prefix
        if (t == 31) stot = z;
    }
    __syncthreads();
    unsigned int P = wsum[wp] + x - s;   // samples strictly above this thread's chunk
    float urv = side ? ur_t[0] : ur_s[0];
    unsigned int K = (unsigned int)(int)(clampf(urv) * (float)NTOK);
    unsigned int sKt = K >> 3;
    unsigned int targHi = (sKt > SMARG) ? (sKt - SMARG) : 0u;
    unsigned int targLo = sKt + SMARG;
    unsigned int total = stot;
    unsigned int cum = P;
    #pragma unroll
    for (int i = 0; i < 8; i++) {
        int bb = 8191 - (t*8 + i);
        unsigned int hv = v[i];
        if (cum <= targHi && cum + hv > targHi) d_bHi[row] = bb;
        if (cum <  targLo && cum + hv >= targLo) d_bLo[row] = bb;
        cum += hv;
    }
    if (t == 0 && targLo > total) d_bLo[row] = 0;
}

// ---------------- k_mask: pipelined loads, aggregated append, private segments ----------------
extern __shared__ unsigned int mbuf[];
__global__ void __launch_bounds__(512, 2) k_mask(const float* __restrict__ u0s,
                                                 const float* __restrict__ u0t,
                                                 float* __restrict__ out)
{
    __shared__ float stab[112];
    __shared__ unsigned int s17[17];
    __shared__ unsigned int sCnt;
    unsigned int* bKey = mbuf;
    unsigned int* bIdx = mbuf + BUFCAP;

    int row   = blockIdx.x >> 3;
    int chunk = blockIdx.x & 7;
    int side  = row >> 5, b = row & 31;
    int t = threadIdx.x;
    if (t < 112) stab[t] = d_tab[side][b][t];
    if (t == 0) sCnt = 0u;
    __syncthreads();

    unsigned int bHi = (unsigned int)d_bHi[row];
    unsigned int bLo = (unsigned int)d_bLo[row];
    unsigned long long hk = ((unsigned long long)(bHi + 1)) << 19;
    float Thif = (hk >= 0x3F800000ull) ? 1.0f : __uint_as_float((unsigned int)hk);
    float Tlof = __uint_as_float(bLo << 19);

    const float4* src = (const float4*)((side ? u0t : u0s) + (size_t)b * NTOK);
    float4* out4 = (float4*)(out + (size_t)row * NTOK);
    unsigned int* segK = &d_candKey[row][chunk * CAPB];
    unsigned int* segI = &d_candIdx[row][chunk * CAPB];
    int lane = t & 31;
    unsigned int lmask = (1u << lane) - 1u;
    unsigned int nAbove = 0;
    unsigned int gTot = 0;               // uniform across block

    int w0 = (t << 2) & 31;
    int h  = (t >> 3) & 31;
    float hC = stab[48 + h];
    float wj0 = stab[80+w0+0] * hC;
    float wj1 = stab[80+w0+1] * hC;
    float wj2 = stab[80+w0+2] * hC;
    float wj3 = stab[80+w0+3] * hC;

#define PROC(u, idx4) do {                                                          \
    float pre = stab[(idx4) >> 13] * stab[16 + (((idx4) >> 8) & 31)];               \
    float k0 = clampf((u).x) * pre * wj0;                                           \
    float k1 = clampf((u).y) * pre * wj1;                                           \
    float k2 = clampf((u).z) * pre * wj2;                                           \
    float k3 = clampf((u).w) * pre * wj3;                                           \
    bool a0 = (k0 >= Thif), a1 = (k1 >= Thif), a2 = (k2 >= Thif), a3 = (k3 >= Thif);\
    nAbove += (unsigned int)a0 + a1 + a2 + a3;                                      \
    unsigned int cm = (unsigned int)(!a0 && k0 >= Tlof)                             \
                    | ((unsigned int)(!a1 && k1 >= Tlof) << 1)                      \
                    | ((unsigned int)(!a2 && k2 >= Tlof) << 2)                      \
                    | ((unsigned int)(!a3 && k3 >= Tlof) << 3);                     \
    unsigned int b0 = __ballot_sync(0xffffffffu, cm & 1u);                          \
    unsigned int b1 = __ballot_sync(0xffffffffu, cm & 2u);                          \
    unsigned int b2 = __ballot_sync(0xffffffffu, cm & 4u);                          \
    unsigned int b3 = __ballot_sync(0xffffffffu, cm & 8u);                          \
    unsigned int c0 = __popc(b0), c1 = __popc(b1), c2 = __popc(b2), c3 = __popc(b3);\
    unsigned int tot = c0 + c1 + c2 + c3;                                           \
    if (tot) {                                                                      \
        unsigned int bp = 0;                                                        \
        if (lane == 0) bp = atomicAdd(&sCnt, tot);                                  \
        bp = __shfl_sync(0xffffffffu, bp, 0);                                       \
        int n = (idx4) << 2;                                                        \
        if (cm & 1u) { unsigned int p = bp + __popc(b0 & lmask);                    \
            if (p < BUFCAP) { bKey[p] = __float_as_uint(k0); bIdx[p] = (unsigned int)n; } } \
        if (cm & 2u) { unsigned int p = bp + c0 + __popc(b1 & lmask);               \
            if (p < BUFCAP) { bKey[p] = __float_as_uint(k1); bIdx[p] = (unsigned int)(n + 1); } } \
        if (cm & 4u) { unsigned int p = bp + c0 + c1 + __popc(b2 & lmask);          \
            if (p < BUFCAP) { bKey[p] = __float_as_uint(k2); bIdx[p] = (unsigned int)(n + 2); } } \
        if (cm & 8u) { unsigned int p = bp + c0 + c1 + c2 + __popc(b3 & lmask);     \
            if (p < BUFCAP) { bKey[p] = __float_as_uint(k3); bIdx[p] = (unsigned int)(n + 3); } } \
    }                                                                               \
    __stcs(&out4[(idx4)], make_float4(a0 ? 1.0f : 0.0f, a1 ? 1.0f : 0.0f,           \
                                      a2 ? 1.0f : 0.0f, a3 ? 1.0f : 0.0f));         \
} while (0)

    int base4 = chunk * 16384;

    // prologue: load group 0
    int i0 = base4 + t;
    float4 u0 = __ldcs(&src[i0]);
    float4 u1 = __ldcs(&src[i0 + 512]);
    float4 u2 = __ldcs(&src[i0 + 1024]);
    float4 u3 = __ldcs(&src[i0 + 1536]);

    for (int itg = 0; itg < 8; itg++) {
        int j0 = base4 + (itg + 1) * 2048 + t;
        float4 n0, n1, n2, n3;
        // prefetch first half of next group
        if (itg < 7) { n0 = __ldcs(&src[j0]); n1 = __ldcs(&src[j0 + 512]); }
        PROC(u0, i0);
        PROC(u1, i0 + 512);
        // prefetch second half of next group
        if (itg < 7) { n2 = __ldcs(&src[j0 + 1024]); n3 = __ldcs(&src[j0 + 1536]); }
        PROC(u2, i0 + 1024);
        PROC(u3, i0 + 1536);

        // flush check once per group (max growth 4*512*4 = 8192)
        __syncthreads();
        unsigned int cur = sCnt;
        if (cur > BUFCAP - 8192u) {
            for (unsigned int i = t; i < cur; i += 512) {
                unsigned int gpos = gTot + i;
                if (gpos < CAPB) { segK[gpos] = bKey[i]; segI[gpos] = bIdx[i]; }
            }
            gTot += cur;
            __syncthreads();
            if (t == 0) sCnt = 0u;
            __syncthreads();
        }

        u0 = n0; u1 = n1; u2 = n2; u3 = n3;
        i0 = j0;
    }
#undef PROC

    {
        unsigned int cur = sCnt;
        for (unsigned int i = t; i < cur; i += 512) {
            unsigned int gpos = gTot + i;
            if (gpos < CAPB) { segK[gpos] = bKey[i]; segI[gpos] = bIdx[i]; }
        }
        gTot += cur;
    }

    unsigned int wv = __reduce_add_sync(0xffffffffu, nAbove);
    if (lane == 0) s17[t >> 5] = wv;
    __syncthreads();
    if (t < 16) {
        unsigned int z = s17[t];
        #pragma unroll
        for (int o = 8; o > 0; o >>= 1) z += __shfl_down_sync(0xffffu, z, o);
        if (t == 0) d_abovePart[row][chunk] = z;
    }
    if (t == 16) d_ccPart[row][chunk] = (gTot < CAPB) ? gTot : CAPB;
}

// ---------------- block reduce helper (fallback path only) ----------------
static __device__ __forceinline__ unsigned int blk_reduce_1024(unsigned int v, unsigned int* s33)
{
    unsigned int wv = __reduce_add_sync(0xffffffffu, v);
    int lane = threadIdx.x & 31, w = threadIdx.x >> 5;
    __syncthreads();
    if (lane == 0) s33[w] = wv;
    __syncthreads();
    if (threadIdx.x < 32) {
        unsigned int x = s33[threadIdx.x];
        x = __reduce_add_sync(0xffffffffu, x);
        if (threadIdx.x == 0) s33[32] = x;
    }
    __syncthreads();
    return s33[32];
}

// ---------------- k_select: smem-resident keys+idx, radix descent + tie-break ----------------
extern __shared__ unsigned int dynsm[];
__global__ void __launch_bounds__(1024) k_select(float* __restrict__ out)
{
    __shared__ unsigned int hcnt[1024];
    __shared__ unsigned int wsum[32];
    __shared__ unsigned int sSel, sRnew;
    __shared__ unsigned int eqIdx[2048];
    __shared__ unsigned int eqCnt;
    __shared__ unsigned int sIstar;
    __shared__ unsigned int s33[33];
    unsigned int* keys = dynsm;
    unsigned int* idxs = dynsm + SELC;

    int row = blockIdx.x, t = threadIdx.x;
    unsigned int cnt[NSEG], off[NSEG];
    unsigned int c = 0, above = 0;
    #pragma unroll
    for (int s = 0; s < NSEG; s++) {
        unsigned int cs = d_ccPart[row][s];
        cnt[s] = (cs < CAPB) ? cs : CAPB;
        off[s] = c;
        c += cnt[s];
        above += d_abovePart[row][s];
    }
    unsigned int K = (unsigned int)d_Kc[row >> 5];
    int R = (int)K - (int)above;
    const unsigned int* gk = d_candKey[row];
    const unsigned int* gi = d_candIdx[row];
    float* orow = out + (size_t)row * NTOK;
    if (R <= 0) return;
    if ((unsigned int)R >= c) {
        #pragma unroll
        for (int s = 0; s < NSEG; s++)
            for (unsigned int i = t; i < cnt[s]; i += 1024)
                orow[gi[s*CAPB + i]] = 1.0f;
        return;
    }

    bool insm = (c <= SELC);
    if (insm) {
        #pragma unroll
        for (int s = 0; s < NSEG; s++)
            for (unsigned int i = t; i < cnt[s]; i += 1024) {
                keys[off[s] + i] = gk[s*CAPB + i];
                idxs[off[s] + i] = gi[s*CAPB + i];
            }
        __syncthreads();
    }

    unsigned int bLo = (unsigned int)d_bLo[row], bHi = (unsigned int)d_bHi[row];
    unsigned int base = bLo << 19;
    unsigned long long Wd = ((unsigned long long)(bHi + 1u - bLo)) << 19;
    int sb = (Wd <= 1ull) ? 0 : (64 - __clzll(Wd - 1ull));
    if (sb > 32) sb = 32;
    unsigned int Rcur = (unsigned int)R;

    while (sb > 0) {
        int bits = sb >= 10 ? 10 : sb;
        int shift = sb - bits;
        hcnt[t] = 0u;
        __syncthreads();
        unsigned int spanm = (sb >= 32) ? 0xFFFFFFFFu : ((1u << sb) - 1u);
        if (insm) {
            for (unsigned int i = t; i < c; i += 1024) {
                unsigned int k = keys[i];
                unsigned int d = k - base;
                if (k >= base && d <= spanm) atomicAdd(&hcnt[d >> shift], 1u);
            }
        } else {
            #pragma unroll
            for (int s = 0; s < NSEG; s++)
                for (unsigned int i = t; i < cnt[s]; i += 1024) {
                    unsigned int k = gk[s*CAPB + i];
                    unsigned int d = k - base;
                    if (k >= base && d <= spanm) atomicAdd(&hcnt[d >> shift], 1u);
                }
        }
        __syncthreads();
        unsigned int x = hcnt[1023 - t];
        unsigned int cb = x;
        int lane = t & 31, w = t >> 5;
        #pragma unroll
        for (int o = 1; o < 32; o <<= 1) {
            unsigned int y = __shfl_up_sync(0xffffffffu, x, o);
            if (lane >= o) x += y;
        }
        if (lane == 31) wsum[w] = x;
        __syncthreads();
        if (t < 32) {
            unsigned int y = wsum[t], z = y;
            #pragma unroll
            for (int o = 1; o < 32; o <<= 1) {
                unsigned int q = __shfl_up_sync(0xffffffffu, z, o);
                if (t >= o) z += q;
            }
            wsum[t] = z - y;
        }
        __syncthreads();
        unsigned int incl = wsum[w] + x;
        unsigned int A = incl - cb;
        if (A < Rcur && Rcur <= incl) { sSel = (unsigned int)(1023 - t); sRnew = Rcur - A; }
        __syncthreads();
        base += sSel << shift;
        Rcur = sRnew;
        sb = shift;
        __syncthreads();
    }
    unsigned int Tkey = base;
    unsigned int R3 = Rcur;   // rank among equal keys (stable by index), >= 1

    if (t == 0) eqCnt = 0u;
    __syncthreads();
    if (insm) {
        for (unsigned int i = t; i < c; i += 1024)
            if (keys[i] == Tkey) {
                unsigned int p = atomicAdd(&eqCnt, 1u);
                if (p < 2048) eqIdx[p] = idxs[i];
            }
    } else {
        #pragma unroll
        for (int s = 0; s < NSEG; s++)
            for (unsigned int i = t; i < cnt[s]; i += 1024)
                if (gk[s*CAPB + i] == Tkey) {
                    unsigned int p = atomicAdd(&eqCnt, 1u);
                    if (p < 2048) eqIdx[p] = gi[s*CAPB + i];
                }
    }
    __syncthreads();
    unsigned int e = eqCnt;
    unsigned int Istar;
    if (e <= 2048) {
        for (unsigned int j = t; j < e; j += 1024) {
            unsigned int my = eqIdx[j], r = 0;
            for (unsigned int m = 0; m < e; m++) r += (eqIdx[m] < my);
            if (r == R3 - 1u) sIstar = my;
        }
        __syncthreads();
        Istar = sIstar;
    } else {
        unsigned int ilo = 0, ihi = NTOK - 1;
        while (ilo < ihi) {
            unsigned int mid = (ilo + ihi) >> 1;
            unsigned int l2 = 0;
            if (insm) {
                for (unsigned int i = t; i < c; i += 1024)
                    if (keys[i] == Tkey) l2 += (idxs[i] <= mid);
            } else {
                #pragma unroll
                for (int s = 0; s < NSEG; s++)
                    for (unsigned int i = t; i < cnt[s]; i += 1024)
                        if (gk[s*CAPB + i] == Tkey) l2 += (gi[s*CAPB + i] <= mid);
            }
            unsigned int cc2 = blk_reduce_1024(l2, s33);
            if (cc2 >= R3) ihi = mid; else ilo = mid + 1u;
        }
        Istar = ilo;
    }

    if (insm) {
        for (unsigned int i = t; i < c; i += 1024) {
            unsigned int k = keys[i];
            if (k > Tkey || (k == Tkey && idxs[i] <= Istar)) orow[idxs[i]] = 1.0f;
        }
    } else {
        #pragma unroll
        for (int s = 0; s < NSEG; s++)
            for (unsigned int i = t; i < cnt[s]; i += 1024) {
                unsigned int k = gk[s*CAPB + i];
                if (k > Tkey || (k == Tkey && gi[s*CAPB + i] <= Istar))
                    orow[gi[s*CAPB + i]] = 1.0f;
            }
    }
}

// ---------------- launch ----------------
extern "C" void kernel_launch(void* const* d_in, const int* in_sizes, int n_in,
                              void* d_out, int out_size)
{
    const float* comps = (const float*)d_in[0];
    const float* ur_s  = (const float*)d_in[1];
    const float* ur_t  = (const float*)d_in[2];
    const float* u0s   = (const float*)d_in[3];
    const float* u0t   = (const float*)d_in[4];
    const float* uv_s  = (const float*)d_in[5];
    const float* ut_s  = (const float*)d_in[6];
    const float* uh_s  = (const float*)d_in[7];
    const float* uw_s  = (const float*)d_in[8];
    const float* uv_t  = (const float*)d_in[9];
    const float* ut_t  = (const float*)d_in[10];
    const float* uh_t  = (const float*)d_in[11];
    const float* uw_t  = (const float*)d_in[12];
    const int*   idx   = (const int*)d_in[13];
    float* out = (float*)d_out;

    static int attr_done = 0;
    if (!attr_done) {
        cudaFuncSetAttribute(k_mask, cudaFuncAttributeMaxDynamicSharedMemorySize,
                             BUFCAP * 2 * sizeof(unsigned int));
        cudaFuncSetAttribute(k_select, cudaFuncAttributeMaxDynamicSharedMemorySize,
                             SELC * 2 * sizeof(unsigned int));
        attr_done = 1;
    }

    k_histscan<<<64, 1024>>>(comps, idx, ur_s, ur_t,
                             uv_s, ut_s, uh_s, uw_s,
                             uv_t, ut_t, uh_t, uw_t,
                             u0s, u0t);
    k_mask<<<512, 512, BUFCAP * 2 * sizeof(unsigned int)>>>(u0s, u0t, out);
    k_select<<<64, 1024, SELC * 2 * sizeof(unsigned int)>>>(out);
}